// round 11
// baseline (speedup 1.0000x reference)
#include <cuda_runtime.h>
#include <cuda_bf16.h>
#include <math.h>

#define BB   16
#define CIN  3
#define SS   16384
#define HID  64
#define NM   16
#define NL   4
#define NPSP 500
#define NPFR 200
#define ED   8
#define NCH  64          // split-K chunks for forward DFT (256 samples each)

// ---------------- scratch (__device__ globals; no allocation) ----------------
__device__ float d_hA[BB * HID * SS];            // 64 MB
__device__ float d_hB[BB * HID * SS];            // 64 MB
__device__ float d_twcT[NM * SS];                // [k][s] cos
__device__ float d_twsT[NM * SS];                // [k][s] sin
__device__ float d_part[BB * NCH * HID * 32];    // split-K partials, 8 MB
__device__ float d_Cf[BB * HID * 32];            // combined scaled spectrum: 0..15 Re', 16..31 Im'
__device__ float d_sC[BB * SS];                  // per-position channel sums (for spatial hash)
__device__ int   d_idx[BB * SS];                 // spatial hash index
__device__ int   d_cnt[BB * NPSP];               // per-batch global histogram
__device__ float d_Pall[NL * NPSP * HID];        // projected spatial patterns, all layers
__device__ float d_gw[BB];                       // gate weight w1 per batch

__device__ __forceinline__ const float* hbuf_c(int s) { return s ? d_hB : d_hA; }
__device__ __forceinline__ float*       hbuf(int s)   { return s ? d_hB : d_hA; }

// ---------------- twiddles (float sinpi/cospi; args 2m/S exact in fp32) ----------------
__global__ void k_init_tw() {
    int i = blockIdx.x * 256 + threadIdx.x;        // i < SS*NM
    int s = i / NM, k = i % NM;
    int m = (s * k) & (SS - 1);
    float x = (float)(2 * m) / (float)SS;
    d_twcT[k * SS + s] = cospif(x);
    d_twsT[k * SS + s] = sinpif(x);
}

// ---------------- all-layer spatial pattern projection + initial d_cnt zero ----------------
__global__ void k_prep_all(const float* __restrict__ sp_emb, const float* __restrict__ sp_W,
                           const float* __restrict__ sp_b) {
    int i = blockIdx.x * 256 + threadIdx.x;        // NL*NPSP*HID = 128000
    if (i < BB * NPSP) d_cnt[i] = 0;
    if (i >= NL * NPSP * HID) return;
    int l = i / (NPSP * HID);
    int r = i - l * (NPSP * HID);
    int p = r / HID, c = r % HID;
    const float* e = sp_emb + (l * NPSP + p) * ED;
    const float* W = sp_W + l * ED * HID;
    float acc = sp_b[l * HID + c];
#pragma unroll
    for (int j = 0; j < ED; j++) acc = fmaf(e[j], W[j * HID + c], acc);
    d_Pall[i] = acc;
}

// ---------------- lift: h = x @ lift_W + lift_b  (+ channel sums for hash) ----------------
__global__ void k_lift(const float* __restrict__ x, const float* __restrict__ W,
                       const float* __restrict__ bias) {
    int i = blockIdx.x * 256 + threadIdx.x;        // over B*S
    int b = i >> 14;
    int s = i & (SS - 1);
    float x0 = x[(b * CIN + 0) * SS + s];
    float x1 = x[(b * CIN + 1) * SS + s];
    float x2 = x[(b * CIN + 2) * SS + s];
    float csum = 0.f;
#pragma unroll
    for (int c = 0; c < HID; c++) {
        float v = fmaf(x0, __ldg(&W[0 * HID + c]),
                  fmaf(x1, __ldg(&W[1 * HID + c]),
                  fmaf(x2, __ldg(&W[2 * HID + c]), __ldg(&bias[c]))));
        d_hA[(b * HID + c) * SS + s] = v;
        csum += v;
    }
    d_sC[b * SS + s] = csum;
}

// ---------------- forward DFT pass 1 + spatial hash ----------------
// grid (NCH=64, B), 256 threads, 256 samples per block in 4 pieces of 64.
// Thread: g = t&15 -> output cols {g, 16+g} (cos_g, sin_g); c4 = t>>4 -> channels {4c4..+3}.
// sh_tw[g][..] / sh_tw[g+16][..]: quarter-lane banks 4g mod 32 -> conflict-free.
__global__ void __launch_bounds__(256) k_fwd1(int src) {
    __shared__ float sh_h[64][68];                 // [channel][s_local]
    __shared__ float sh_tw[32][68];                // [col][s_local] (0..15 cos, 16..31 sin)
    __shared__ int hist[NPSP];
    const float* h = hbuf_c(src);
    int chunk = blockIdx.x, b = blockIdx.y, t = threadIdx.x;
    int g = t & 15;
    int c4 = t >> 4;
    int s0 = chunk * 256;

    // ---- spatial hash for this block's 256 samples (d_sC ready from lift/comb) ----
    for (int i = t; i < NPSP; i += 256) hist[i] = 0;
    __syncthreads();
    {
        int s = s0 + t;
        const float* sc = d_sC + b * SS;
        int a0 = max(s - 2, 0), a1 = max(s - 1, 0), a3 = min(s + 1, SS - 1);
        float w = ((sc[a0] + sc[a1]) + sc[s]) + sc[a3];
        int iv = (int)(w * 31.0f);
        int m = iv % NPSP; if (m < 0) m += NPSP;
        d_idx[b * SS + s] = m;
        atomicAdd(&hist[m], 1);
    }
    __syncthreads();
    for (int i = t; i < NPSP; i += 256)
        if (hist[i]) atomicAdd(&d_cnt[b * NPSP + i], hist[i]);

    // ---- DFT partial GEMM ----
    float a00 = 0.f, a01 = 0.f, a10 = 0.f, a11 = 0.f;
    float a20 = 0.f, a21 = 0.f, a30 = 0.f, a31 = 0.f;

    for (int piece = 0; piece < 4; piece++) {
        int sp0 = s0 + piece * 64;
        for (int u = t; u < 1024; u += 256) {
            int cc = u >> 4;
            int s4 = (u & 15) * 4;
            *(float4*)&sh_h[cc][s4] = *(const float4*)&h[(b * HID + cc) * SS + sp0 + s4];
        }
        for (int u = t; u < 512; u += 256) {
            int col = u >> 4;
            int s4 = (u & 15) * 4;
            float4 v;
            if (col < 16) v = *(const float4*)&d_twcT[col * SS + sp0 + s4];
            else          v = *(const float4*)&d_twsT[(col - 16) * SS + sp0 + s4];
            *(float4*)&sh_tw[col][s4] = v;
        }
        __syncthreads();
#pragma unroll
        for (int q = 0; q < 16; q++) {
            float4 t0 = *(const float4*)&sh_tw[g][q * 4];        // cos col g
            float4 t1 = *(const float4*)&sh_tw[g + 16][q * 4];   // sin col g
            float4 hv;
            hv = *(const float4*)&sh_h[c4 * 4 + 0][q * 4];
            a00 = fmaf(hv.x, t0.x, fmaf(hv.y, t0.y, fmaf(hv.z, t0.z, fmaf(hv.w, t0.w, a00))));
            a01 = fmaf(hv.x, t1.x, fmaf(hv.y, t1.y, fmaf(hv.z, t1.z, fmaf(hv.w, t1.w, a01))));
            hv = *(const float4*)&sh_h[c4 * 4 + 1][q * 4];
            a10 = fmaf(hv.x, t0.x, fmaf(hv.y, t0.y, fmaf(hv.z, t0.z, fmaf(hv.w, t0.w, a10))));
            a11 = fmaf(hv.x, t1.x, fmaf(hv.y, t1.y, fmaf(hv.z, t1.z, fmaf(hv.w, t1.w, a11))));
            hv = *(const float4*)&sh_h[c4 * 4 + 2][q * 4];
            a20 = fmaf(hv.x, t0.x, fmaf(hv.y, t0.y, fmaf(hv.z, t0.z, fmaf(hv.w, t0.w, a20))));
            a21 = fmaf(hv.x, t1.x, fmaf(hv.y, t1.y, fmaf(hv.z, t1.z, fmaf(hv.w, t1.w, a21))));
            hv = *(const float4*)&sh_h[c4 * 4 + 3][q * 4];
            a30 = fmaf(hv.x, t0.x, fmaf(hv.y, t0.y, fmaf(hv.z, t0.z, fmaf(hv.w, t0.w, a30))));
            a31 = fmaf(hv.x, t1.x, fmaf(hv.y, t1.y, fmaf(hv.z, t1.z, fmaf(hv.w, t1.w, a31))));
        }
        __syncthreads();
    }
    float* p = &d_part[((size_t)(b * NCH + chunk) * HID + c4 * 4) * 32];
    p[0 * 32 + g] = a00;  p[0 * 32 + 16 + g] = a01;
    p[1 * 32 + g] = a10;  p[1 * 32 + 16 + g] = a11;
    p[2 * 32 + g] = a20;  p[2 * 32 + 16 + g] = a21;
    p[3 * 32 + g] = a30;  p[3 * 32 + 16 + g] = a31;
}

// ---------------- per-batch: DFT reduce + spectral mix + gate + combined spectrum ----------------
__global__ void __launch_bounds__(256) k_mix(
        const float* __restrict__ fr_emb, const float* __restrict__ fr_W,
        const float* __restrict__ fr_b,
        const float* __restrict__ mhf_Wr, const float* __restrict__ mhf_Wi,
        const float* __restrict__ gW1, const float* __restrict__ gb1,
        const float* __restrict__ gW2, const float* __restrict__ gb2,
        int layer) {
    __shared__ float shX[HID * 32];
    __shared__ float shMHre[HID * NM];
    __shared__ float shMHim[HID * NM];
    __shared__ float shFR[HID * NM];
    __shared__ double shmagp[4][16];
    __shared__ double shgp[4][64];
    __shared__ float shg[192];
    __shared__ float shhid[64];
    __shared__ float shw[3];
    __shared__ int   shmi[16];
    __shared__ int   sh_ifr;
    int b = blockIdx.x, t = threadIdx.x;

    // Phase A: deterministic fp64 reduction of split-K partials (fixed chunk order)
    for (int u = t; u < HID * 32; u += 256) {
        double acc = 0.0;
        const float* p = d_part + (size_t)b * NCH * 2048 + u;
#pragma unroll 8
        for (int ch = 0; ch < NCH; ch++) acc += (double)p[ch * 2048];
        shX[u] = (float)acc;
    }
    __syncthreads();

    // spectral magnitude hash: 4 fixed-order fp64 slices of 16 channels
    if (t < 64) {
        int k = t & 15, sl = t >> 4;
        double acc = 0.0;
        for (int c = sl * 16; c < sl * 16 + 16; c++) {
            double re = (double)shX[c * 32 + k];
            double im = (double)shX[c * 32 + 16 + k];
            acc += sqrt(re * re + im * im);
        }
        shmagp[sl][k] = acc;
    }
    // multi-head Fourier mix
    for (int u = t; u < 1024; u += 256) {            // u = h*256 + o*16 + k
        int h_ = u >> 8, o = (u >> 4) & 15, k = u & 15;
        float ar = 0.f, ai = 0.f;
        const float* Wr = mhf_Wr + (((layer * 4 + h_) * 16) * 16 + o) * 16 + k;
        const float* Wi = mhf_Wi + (((layer * 4 + h_) * 16) * 16 + o) * 16 + k;
#pragma unroll
        for (int i = 0; i < 16; i++) {
            int cin = h_ * 16 + i;
            float re = shX[cin * 32 + k];
            float im = -shX[cin * 32 + 16 + k];
            float wr = Wr[i * 256];
            float wi = Wi[i * 256];
            ar = fmaf(re, wr, ar); ar = fmaf(-im, wi, ar);
            ai = fmaf(re, wi, ai); ai = fmaf(im, wr, ai);
        }
        int cout = h_ * 16 + o;
        shMHre[cout * 16 + k] = ar;
        shMHim[cout * 16 + k] = ai;
    }
    __syncthreads();
    if (t < 16) {
        double acc = ((shmagp[0][t] + shmagp[1][t]) + shmagp[2][t]) + shmagp[3][t];
        float mag = (float)(acc / 64.0);
        shmi[t] = (int)(mag * 1000.0f);
    }
    __syncthreads();
    if (t == 0) {
        int ssum = 0;
        for (int k = 0; k < 16; k++) ssum += shmi[k];
        int m = ssum % NPFR; if (m < 0) m += NPFR;
        sh_ifr = m;
    }
    __syncthreads();
    // spectral engram projection
    {
        const float* e = fr_emb + (layer * NPFR + sh_ifr) * ED;
        for (int u = t; u < 1024; u += 256) {        // u = c*16+k
            const float* W = fr_W + layer * ED * 1024 + u;
            float acc = fr_b[layer * 1024 + u];
#pragma unroll
            for (int j = 0; j < ED; j++) acc = fmaf(e[j], W[j * 1024], acc);
            shFR[u] = acc;
        }
    }
    // gate spatial mean: 4 fixed-order fp64 slices of 125 patterns
    {
        int c = t & 63, sl = t >> 6;
        double acc = 0.0;
        const float* P = d_Pall + layer * NPSP * HID;
        const int* cnt = d_cnt + b * NPSP;
        for (int p = sl * 125; p < sl * 125 + 125; p++)
            acc += (double)cnt[p] * (double)P[p * HID + c];
        shgp[sl][c] = acc;
    }
    __syncthreads();
    // all d_cnt reads complete -> zero it for the next layer's fwd1
    for (int i = t; i < NPSP; i += 256) d_cnt[b * NPSP + i] = 0;
    if (t < 64) {
        double acc = ((shgp[0][t] + shgp[1][t]) + shgp[2][t]) + shgp[3][t];
        shg[t]       = (float)(acc / (double)SS);
        shg[64 + t]  = shMHre[t * 16 + 0] / (float)SS;
        shg[128 + t] = shFR[t * 16 + 0] / (float)SS;
    }
    __syncthreads();
    if (t < 64) {
        float acc = gb1[layer * 64 + t];
        const float* W1 = gW1 + layer * 192 * 64;
        for (int j = 0; j < 192; j++) acc = fmaf(shg[j], W1[j * 64 + t], acc);
        shhid[t] = fmaxf(acc, 0.f);
    }
    __syncthreads();
    if (t == 0) {
        float lg[3];
        const float* W2 = gW2 + layer * 64 * 3;
        for (int o = 0; o < 3; o++) {
            float acc = gb2[layer * 3 + o];
            for (int j = 0; j < 64; j++) acc = fmaf(shhid[j], W2[j * 3 + o], acc);
            lg[o] = acc;
        }
        float mx = fmaxf(lg[0], fmaxf(lg[1], lg[2]));
        float e0 = expf(lg[0] - mx), e1 = expf(lg[1] - mx), e2 = expf(lg[2] - mx);
        float inv = 1.f / (e0 + e1 + e2);
        shw[0] = e0 * inv; shw[1] = e1 * inv; shw[2] = e2 * inv;
        d_gw[b] = shw[0];
    }
    __syncthreads();
    // combined, irfft-prescaled spectrum
    float w2 = shw[1], w3 = shw[2];
    for (int u = t; u < 1024; u += 256) {            // u = c*16+k
        int k = u & 15;
        int c = u >> 4;
        float sc = ((k == 0) ? 1.f : 2.f) / (float)SS;
        d_Cf[(b * HID + c) * 32 + k]      = (w2 * shMHre[u] + w3 * shFR[u]) * sc;
        d_Cf[(b * HID + c) * 32 + 16 + k] = (w2 * shMHim[u]) * sc;
    }
}

// ---------------- combine (GEMM-structured inverse DFT + engram + gelu) ----------------
// h[c][s] = gelu( w1*P[idx[s]][c] + sum_K A[K][c]*T[K][s] ),  A = [Cr | -Ci], T = [cos | sin].
// Thread tile: 4 channels (c4) x 4 samples (sg). Layers 0..2 write h + channel sums;
// layer 3 fuses the output projection.
__global__ void __launch_bounds__(256) k_comb(int dst, int layer,
                                              const float* __restrict__ projW,
                                              const float* __restrict__ projb,
                                              float* __restrict__ out) {
    __shared__ float shA[32][68];                  // [K][channel]
    __shared__ float shT[32][68];                  // [K][s_local]
    __shared__ float shCS[16 * 64];                // per-c4 partial channel sums
    float* hn = hbuf(dst);
    int b = blockIdx.y, chunk = blockIdx.x, t = threadIdx.x;
    int sg = t & 15, c4 = t >> 4;
    int s0 = chunk * 256;
    bool last = (layer == NL - 1);

    for (int u = t; u < 2048; u += 256) {
        int K = u >> 6, c = u & 63;
        float v = (K < 16) ? d_Cf[b * 2048 + c * 32 + K]
                           : -d_Cf[b * 2048 + c * 32 + 16 + (K - 16)];
        shA[K][c] = v;
    }
    float w1 = d_gw[b];
    float pw0 = 1.f, pw1 = 1.f, pw2 = 1.f, pw3 = 1.f;
    if (last) {
        pw0 = __ldg(&projW[c4 * 4 + 0]); pw1 = __ldg(&projW[c4 * 4 + 1]);
        pw2 = __ldg(&projW[c4 * 4 + 2]); pw3 = __ldg(&projW[c4 * 4 + 3]);
    }

    for (int piece = 0; piece < 4; piece++) {
        int sp0 = s0 + piece * 64;
        for (int u = t; u < 512; u += 256) {
            int K = u >> 4, s4 = (u & 15) * 4;
            float4 v;
            if (K < 16) v = *(const float4*)&d_twcT[K * SS + sp0 + s4];
            else        v = *(const float4*)&d_twsT[(K - 16) * SS + sp0 + s4];
            *(float4*)&shT[K][s4] = v;
        }
        __syncthreads();

        float acc[4][4];
#pragma unroll
        for (int ci = 0; ci < 4; ci++)
#pragma unroll
            for (int si = 0; si < 4; si++) acc[ci][si] = 0.f;

#pragma unroll
        for (int K = 0; K < 32; K++) {
            float4 a  = *(const float4*)&shA[K][c4 * 4];
            float4 tv = *(const float4*)&shT[K][sg * 4];
            acc[0][0] = fmaf(a.x, tv.x, acc[0][0]); acc[0][1] = fmaf(a.x, tv.y, acc[0][1]);
            acc[0][2] = fmaf(a.x, tv.z, acc[0][2]); acc[0][3] = fmaf(a.x, tv.w, acc[0][3]);
            acc[1][0] = fmaf(a.y, tv.x, acc[1][0]); acc[1][1] = fmaf(a.y, tv.y, acc[1][1]);
            acc[1][2] = fmaf(a.y, tv.z, acc[1][2]); acc[1][3] = fmaf(a.y, tv.w, acc[1][3]);
            acc[2][0] = fmaf(a.z, tv.x, acc[2][0]); acc[2][1] = fmaf(a.z, tv.y, acc[2][1]);
            acc[2][2] = fmaf(a.z, tv.z, acc[2][2]); acc[2][3] = fmaf(a.z, tv.w, acc[2][3]);
            acc[3][0] = fmaf(a.w, tv.x, acc[3][0]); acc[3][1] = fmaf(a.w, tv.y, acc[3][1]);
            acc[3][2] = fmaf(a.w, tv.z, acc[3][2]); acc[3][3] = fmaf(a.w, tv.w, acc[3][3]);
        }

        // epilogue: engram add + exact gelu + partial channel/proj sums
        int4 iv = *(const int4*)&d_idx[b * SS + sp0 + sg * 4];
        int ids[4] = {iv.x, iv.y, iv.z, iv.w};
        float ps[4];
#pragma unroll
        for (int si = 0; si < 4; si++) {
            float4 P = *(const float4*)&d_Pall[(layer * NPSP + ids[si]) * HID + c4 * 4];
            float v0 = fmaf(w1, P.x, acc[0][si]);
            float v1 = fmaf(w1, P.y, acc[1][si]);
            float v2 = fmaf(w1, P.z, acc[2][si]);
            float v3 = fmaf(w1, P.w, acc[3][si]);
            float g0 = 0.5f * v0 * (1.f + erff(v0 * 0.70710678118654752f));
            float g1 = 0.5f * v1 * (1.f + erff(v1 * 0.70710678118654752f));
            float g2 = 0.5f * v2 * (1.f + erff(v2 * 0.70710678118654752f));
            float g3 = 0.5f * v3 * (1.f + erff(v3 * 0.70710678118654752f));
            acc[0][si] = g0; acc[1][si] = g1; acc[2][si] = g2; acc[3][si] = g3;
            ps[si] = fmaf(g0, pw0, fmaf(g1, pw1, fmaf(g2, pw2, g3 * pw3)));
        }
        if (!last) {
#pragma unroll
            for (int ci = 0; ci < 4; ci++) {
                float4 st = make_float4(acc[ci][0], acc[ci][1], acc[ci][2], acc[ci][3]);
                *(float4*)&hn[(b * HID + c4 * 4 + ci) * SS + sp0 + sg * 4] = st;
            }
        }
        *(float4*)&shCS[c4 * 64 + sg * 4] = make_float4(ps[0], ps[1], ps[2], ps[3]);
        __syncthreads();
        if (t < 64) {
            float ss = 0.f;
#pragma unroll
            for (int q = 0; q < 16; q++) ss += shCS[q * 64 + t];   // fixed order
            if (last) out[b * SS + sp0 + t] = ss + projb[0];
            else      d_sC[b * SS + sp0 + t] = ss;
        }
        __syncthreads();
    }
}

// ---------------- host ----------------
extern "C" void kernel_launch(void* const* d_in, const int* in_sizes, int n_in,
                              void* d_out, int out_size) {
    const float* x      = (const float*)d_in[0];
    const float* lift_W = (const float*)d_in[1];
    const float* lift_b = (const float*)d_in[2];
    const float* proj_W = (const float*)d_in[3];
    const float* proj_b = (const float*)d_in[4];
    const float* sp_emb = (const float*)d_in[5];
    const float* sp_W   = (const float*)d_in[6];
    const float* sp_b   = (const float*)d_in[7];
    const float* fr_emb = (const float*)d_in[8];
    const float* fr_W   = (const float*)d_in[9];
    const float* fr_b   = (const float*)d_in[10];
    const float* gW1    = (const float*)d_in[11];
    const float* gb1    = (const float*)d_in[12];
    const float* gW2    = (const float*)d_in[13];
    const float* gb2    = (const float*)d_in[14];
    const float* mhf_Wr = (const float*)d_in[15];
    const float* mhf_Wi = (const float*)d_in[16];
    float* out = (float*)d_out;

    k_init_tw<<<(SS * NM) / 256, 256>>>();
    k_prep_all<<<(NL * NPSP * HID + 255) / 256, 256>>>(sp_emb, sp_W, sp_b);
    k_lift<<<(BB * SS) / 256, 256>>>(x, lift_W, lift_b);

    int src = 0;
    for (int layer = 0; layer < NL; layer++) {
        int dst = src ^ 1;
        k_fwd1<<<dim3(NCH, BB), 256>>>(src);
        k_mix<<<BB, 256>>>(fr_emb, fr_W, fr_b, mhf_Wr, mhf_Wi, gW1, gb1, gW2, gb2, layer);
        k_comb<<<dim3(64, BB), 256>>>(dst, layer, proj_W, proj_b, out);
        src = dst;
    }
}

// round 12
// speedup vs baseline: 1.4878x; 1.4878x over previous
#include <cuda_runtime.h>
#include <cuda_bf16.h>
#include <math.h>

#define BB   16
#define CIN  3
#define SS   16384
#define HID  64
#define NM   16
#define NL   4
#define NPSP 500
#define NPFR 200
#define ED   8
#define NCH  64          // split-K chunks for forward DFT (256 samples each)

// ---------------- scratch (__device__ globals; no allocation) ----------------
__device__ float d_hA[BB * HID * SS];            // 64 MB (layer-0 h only)
__device__ float d_twcT[NM * SS];                // [k][s] cos
__device__ float d_twsT[NM * SS];                // [k][s] sin
__device__ float d_part[BB * NCH * HID * 32];    // split-K partials, 8 MB
__device__ float d_Xf[BB * HID * 32];            // reduced spectrum
__device__ float d_Cf[BB * HID * 32];            // combined scaled spectrum: 0..15 Re', 16..31 Im'
__device__ float d_sC[BB * SS];                  // per-position channel sums (for spatial hash)
__device__ int   d_idx[BB * SS];                 // spatial hash index
__device__ int   d_cnt[BB * NPSP];               // per-batch global histogram
__device__ float d_Pall[NL * NPSP * HID];        // projected spatial patterns, all layers
__device__ float d_gw[BB];                       // gate weight w1 per batch

// ---------------- twiddles (float sinpi/cospi; args 2m/S exact in fp32) ----------------
__global__ void k_init_tw() {
    int i = blockIdx.x * 256 + threadIdx.x;        // i < SS*NM
    int s = i / NM, k = i % NM;
    int m = (s * k) & (SS - 1);
    float x = (float)(2 * m) / (float)SS;
    d_twcT[k * SS + s] = cospif(x);
    d_twsT[k * SS + s] = sinpif(x);
}

// ---------------- all-layer spatial pattern projection + initial d_cnt zero ----------------
__global__ void k_prep_all(const float* __restrict__ sp_emb, const float* __restrict__ sp_W,
                           const float* __restrict__ sp_b) {
    int i = blockIdx.x * 256 + threadIdx.x;        // NL*NPSP*HID = 128000
    if (i < BB * NPSP) d_cnt[i] = 0;
    if (i >= NL * NPSP * HID) return;
    int l = i / (NPSP * HID);
    int r = i - l * (NPSP * HID);
    int p = r / HID, c = r % HID;
    const float* e = sp_emb + (l * NPSP + p) * ED;
    const float* W = sp_W + l * ED * HID;
    float acc = sp_b[l * HID + c];
#pragma unroll
    for (int j = 0; j < ED; j++) acc = fmaf(e[j], W[j * HID + c], acc);
    d_Pall[i] = acc;
}

// ---------------- lift: h0 = x @ lift_W + lift_b  (+ channel sums for hash) ----------------
__global__ void k_lift(const float* __restrict__ x, const float* __restrict__ W,
                       const float* __restrict__ bias) {
    int i = blockIdx.x * 256 + threadIdx.x;        // over B*S
    int b = i >> 14;
    int s = i & (SS - 1);
    float x0 = x[(b * CIN + 0) * SS + s];
    float x1 = x[(b * CIN + 1) * SS + s];
    float x2 = x[(b * CIN + 2) * SS + s];
    float csum = 0.f;
#pragma unroll
    for (int c = 0; c < HID; c++) {
        float v = fmaf(x0, __ldg(&W[0 * HID + c]),
                  fmaf(x1, __ldg(&W[1 * HID + c]),
                  fmaf(x2, __ldg(&W[2 * HID + c]), __ldg(&bias[c]))));
        d_hA[(b * HID + c) * SS + s] = v;
        csum += v;
    }
    d_sC[b * SS + s] = csum;
}

// ---------------- layer-0 forward DFT pass 1 + spatial hash (reads d_hA) ----------------
// Thread: g = t&15 -> output cols {g, 16+g}; c4 = t>>4 -> channels {4c4..+3}.
__global__ void __launch_bounds__(256) k_fwd1() {
    __shared__ float sh_h[64][68];                 // [channel][s_local]
    __shared__ float sh_tw[32][68];                // [col][s_local] (0..15 cos, 16..31 sin)
    __shared__ int hist[NPSP];
    int chunk = blockIdx.x, b = blockIdx.y, t = threadIdx.x;
    int g = t & 15;
    int c4 = t >> 4;
    int s0 = chunk * 256;

    // spatial hash for this block's 256 samples (d_sC ready from lift)
    for (int i = t; i < NPSP; i += 256) hist[i] = 0;
    __syncthreads();
    {
        int s = s0 + t;
        const float* sc = d_sC + b * SS;
        int a0 = max(s - 2, 0), a1 = max(s - 1, 0), a3 = min(s + 1, SS - 1);
        float w = ((sc[a0] + sc[a1]) + sc[s]) + sc[a3];
        int iv = (int)(w * 31.0f);
        int m = iv % NPSP; if (m < 0) m += NPSP;
        d_idx[b * SS + s] = m;
        atomicAdd(&hist[m], 1);
    }
    __syncthreads();
    for (int i = t; i < NPSP; i += 256)
        if (hist[i]) atomicAdd(&d_cnt[b * NPSP + i], hist[i]);

    float a00 = 0.f, a01 = 0.f, a10 = 0.f, a11 = 0.f;
    float a20 = 0.f, a21 = 0.f, a30 = 0.f, a31 = 0.f;

    for (int piece = 0; piece < 4; piece++) {
        int sp0 = s0 + piece * 64;
        for (int u = t; u < 1024; u += 256) {
            int cc = u >> 4;
            int s4 = (u & 15) * 4;
            *(float4*)&sh_h[cc][s4] = *(const float4*)&d_hA[(b * HID + cc) * SS + sp0 + s4];
        }
        for (int u = t; u < 512; u += 256) {
            int col = u >> 4;
            int s4 = (u & 15) * 4;
            float4 v;
            if (col < 16) v = *(const float4*)&d_twcT[col * SS + sp0 + s4];
            else          v = *(const float4*)&d_twsT[(col - 16) * SS + sp0 + s4];
            *(float4*)&sh_tw[col][s4] = v;
        }
        __syncthreads();
#pragma unroll
        for (int q = 0; q < 16; q++) {
            float4 t0 = *(const float4*)&sh_tw[g][q * 4];
            float4 t1 = *(const float4*)&sh_tw[g + 16][q * 4];
            float4 hv;
            hv = *(const float4*)&sh_h[c4 * 4 + 0][q * 4];
            a00 = fmaf(hv.x, t0.x, fmaf(hv.y, t0.y, fmaf(hv.z, t0.z, fmaf(hv.w, t0.w, a00))));
            a01 = fmaf(hv.x, t1.x, fmaf(hv.y, t1.y, fmaf(hv.z, t1.z, fmaf(hv.w, t1.w, a01))));
            hv = *(const float4*)&sh_h[c4 * 4 + 1][q * 4];
            a10 = fmaf(hv.x, t0.x, fmaf(hv.y, t0.y, fmaf(hv.z, t0.z, fmaf(hv.w, t0.w, a10))));
            a11 = fmaf(hv.x, t1.x, fmaf(hv.y, t1.y, fmaf(hv.z, t1.z, fmaf(hv.w, t1.w, a11))));
            hv = *(const float4*)&sh_h[c4 * 4 + 2][q * 4];
            a20 = fmaf(hv.x, t0.x, fmaf(hv.y, t0.y, fmaf(hv.z, t0.z, fmaf(hv.w, t0.w, a20))));
            a21 = fmaf(hv.x, t1.x, fmaf(hv.y, t1.y, fmaf(hv.z, t1.z, fmaf(hv.w, t1.w, a21))));
            hv = *(const float4*)&sh_h[c4 * 4 + 3][q * 4];
            a30 = fmaf(hv.x, t0.x, fmaf(hv.y, t0.y, fmaf(hv.z, t0.z, fmaf(hv.w, t0.w, a30))));
            a31 = fmaf(hv.x, t1.x, fmaf(hv.y, t1.y, fmaf(hv.z, t1.z, fmaf(hv.w, t1.w, a31))));
        }
        __syncthreads();
    }
    float* p = &d_part[((size_t)(b * NCH + chunk) * HID + c4 * 4) * 32];
    p[0 * 32 + g] = a00;  p[0 * 32 + 16 + g] = a01;
    p[1 * 32 + g] = a10;  p[1 * 32 + 16 + g] = a11;
    p[2 * 32 + g] = a20;  p[2 * 32 + 16 + g] = a21;
    p[3 * 32 + g] = a30;  p[3 * 32 + 16 + g] = a31;
}

// ---------------- forward DFT pass 2 (deterministic fp64 reduction, 128 blocks) ----------------
__global__ void k_fwd2() {
    int i = blockIdx.x * 256 + threadIdx.x;        // B*HID*32 = 32768
    int b = i >> 11;
    int rest = i & 2047;
    const float* p = d_part + (size_t)b * NCH * 2048 + rest;
    double acc = 0.0;
#pragma unroll 8
    for (int ch = 0; ch < NCH; ch++) acc += (double)p[ch * 2048];
    d_Xf[i] = (float)acc;
}

// ---------------- spatial hash + histogram (for fused transitions) ----------------
__global__ void __launch_bounds__(256) k_hash() {
    __shared__ int hist[NPSP];
    int b = blockIdx.y, chunk = blockIdx.x, t = threadIdx.x;
    for (int i = t; i < NPSP; i += 256) hist[i] = 0;
    __syncthreads();
    int s = chunk * 256 + t;
    const float* sc = d_sC + b * SS;
    int a0 = max(s - 2, 0), a1 = max(s - 1, 0), a3 = min(s + 1, SS - 1);
    float w = ((sc[a0] + sc[a1]) + sc[s]) + sc[a3];
    int iv = (int)(w * 31.0f);
    int m = iv % NPSP; if (m < 0) m += NPSP;
    d_idx[b * SS + s] = m;
    atomicAdd(&hist[m], 1);
    __syncthreads();
    for (int i = t; i < NPSP; i += 256)
        if (hist[i]) atomicAdd(&d_cnt[b * NPSP + i], hist[i]);
}

// ---------------- per-batch: spectral mix + gate + combined spectrum ----------------
__global__ void __launch_bounds__(256) k_mix(
        const float* __restrict__ fr_emb, const float* __restrict__ fr_W,
        const float* __restrict__ fr_b,
        const float* __restrict__ mhf_Wr, const float* __restrict__ mhf_Wi,
        const float* __restrict__ gW1, const float* __restrict__ gb1,
        const float* __restrict__ gW2, const float* __restrict__ gb2,
        int layer) {
    __shared__ float shX[HID * 32];
    __shared__ float shMHre[HID * NM];
    __shared__ float shMHim[HID * NM];
    __shared__ float shFR[HID * NM];
    __shared__ double shmagp[4][16];
    __shared__ double shgp[4][64];
    __shared__ float shg[192];
    __shared__ float shhid[64];
    __shared__ float shw[3];
    __shared__ int   shmi[16];
    __shared__ int   sh_ifr;
    int b = blockIdx.x, t = threadIdx.x;

    for (int i = t; i < HID * 32; i += 256) shX[i] = d_Xf[b * HID * 32 + i];
    __syncthreads();

    // spectral magnitude hash: 4 fixed-order fp64 slices of 16 channels
    if (t < 64) {
        int k = t & 15, sl = t >> 4;
        double acc = 0.0;
        for (int c = sl * 16; c < sl * 16 + 16; c++) {
            double re = (double)shX[c * 32 + k];
            double im = (double)shX[c * 32 + 16 + k];
            acc += sqrt(re * re + im * im);
        }
        shmagp[sl][k] = acc;
    }
    // multi-head Fourier mix
    for (int u = t; u < 1024; u += 256) {            // u = h*256 + o*16 + k
        int h_ = u >> 8, o = (u >> 4) & 15, k = u & 15;
        float ar = 0.f, ai = 0.f;
        const float* Wr = mhf_Wr + (((layer * 4 + h_) * 16) * 16 + o) * 16 + k;
        const float* Wi = mhf_Wi + (((layer * 4 + h_) * 16) * 16 + o) * 16 + k;
#pragma unroll
        for (int i = 0; i < 16; i++) {
            int cin = h_ * 16 + i;
            float re = shX[cin * 32 + k];
            float im = -shX[cin * 32 + 16 + k];
            float wr = Wr[i * 256];
            float wi = Wi[i * 256];
            ar = fmaf(re, wr, ar); ar = fmaf(-im, wi, ar);
            ai = fmaf(re, wi, ai); ai = fmaf(im, wr, ai);
        }
        int cout = h_ * 16 + o;
        shMHre[cout * 16 + k] = ar;
        shMHim[cout * 16 + k] = ai;
    }
    __syncthreads();
    if (t < 16) {
        double acc = ((shmagp[0][t] + shmagp[1][t]) + shmagp[2][t]) + shmagp[3][t];
        float mag = (float)(acc / 64.0);
        shmi[t] = (int)(mag * 1000.0f);
    }
    __syncthreads();
    if (t == 0) {
        int ssum = 0;
        for (int k = 0; k < 16; k++) ssum += shmi[k];
        int m = ssum % NPFR; if (m < 0) m += NPFR;
        sh_ifr = m;
    }
    __syncthreads();
    // spectral engram projection
    {
        const float* e = fr_emb + (layer * NPFR + sh_ifr) * ED;
        for (int u = t; u < 1024; u += 256) {        // u = c*16+k
            const float* W = fr_W + layer * ED * 1024 + u;
            float acc = fr_b[layer * 1024 + u];
#pragma unroll
            for (int j = 0; j < ED; j++) acc = fmaf(e[j], W[j * 1024], acc);
            shFR[u] = acc;
        }
    }
    // gate spatial mean: 4 fixed-order fp64 slices of 125 patterns
    {
        int c = t & 63, sl = t >> 6;
        double acc = 0.0;
        const float* P = d_Pall + layer * NPSP * HID;
        const int* cnt = d_cnt + b * NPSP;
        for (int p = sl * 125; p < sl * 125 + 125; p++)
            acc += (double)cnt[p] * (double)P[p * HID + c];
        shgp[sl][c] = acc;
    }
    __syncthreads();
    // all d_cnt reads complete -> zero it for the next layer's hash
    for (int i = t; i < NPSP; i += 256) d_cnt[b * NPSP + i] = 0;
    if (t < 64) {
        double acc = ((shgp[0][t] + shgp[1][t]) + shgp[2][t]) + shgp[3][t];
        shg[t]       = (float)(acc / (double)SS);
        shg[64 + t]  = shMHre[t * 16 + 0] / (float)SS;
        shg[128 + t] = shFR[t * 16 + 0] / (float)SS;
    }
    __syncthreads();
    if (t < 64) {
        float acc = gb1[layer * 64 + t];
        const float* W1 = gW1 + layer * 192 * 64;
        for (int j = 0; j < 192; j++) acc = fmaf(shg[j], W1[j * 64 + t], acc);
        shhid[t] = fmaxf(acc, 0.f);
    }
    __syncthreads();
    if (t == 0) {
        float lg[3];
        const float* W2 = gW2 + layer * 64 * 3;
        for (int o = 0; o < 3; o++) {
            float acc = gb2[layer * 3 + o];
            for (int j = 0; j < 64; j++) acc = fmaf(shhid[j], W2[j * 3 + o], acc);
            lg[o] = acc;
        }
        float mx = fmaxf(lg[0], fmaxf(lg[1], lg[2]));
        float e0 = expf(lg[0] - mx), e1 = expf(lg[1] - mx), e2 = expf(lg[2] - mx);
        float inv = 1.f / (e0 + e1 + e2);
        shw[0] = e0 * inv; shw[1] = e1 * inv; shw[2] = e2 * inv;
        d_gw[b] = shw[0];
    }
    __syncthreads();
    // combined, irfft-prescaled spectrum
    float w2 = shw[1], w3 = shw[2];
    for (int u = t; u < 1024; u += 256) {            // u = c*16+k
        int k = u & 15;
        int c = u >> 4;
        float sc = ((k == 0) ? 1.f : 2.f) / (float)SS;
        d_Cf[(b * HID + c) * 32 + k]      = (w2 * shMHre[u] + w3 * shFR[u]) * sc;
        d_Cf[(b * HID + c) * 32 + 16 + k] = (w2 * shMHim[u]) * sc;
    }
}

// ---------------- fused transition: comb(layer) -> gelu tile in smem -> fwd partials ----------------
// comb: h[c][s] = gelu( w1*P[idx[s]][c] + sum_K A[K][c]*T[K][s] );  then immediately
// DFT partials of the new h using the SAME T tile. h never hits global memory.
__global__ void __launch_bounds__(256) k_fused(int layer) {
    __shared__ float shA[32][68];                  // [K][channel]
    __shared__ float shT[32][68];                  // [K][s_local] (0..15 cos, 16..31 sin)
    __shared__ float sh_h[64][68];                 // new h tile [channel][s_local]
    __shared__ float shCS[16 * 64];                // per-c4 partial channel sums
    int b = blockIdx.y, chunk = blockIdx.x, t = threadIdx.x;
    int sg = t & 15, c4 = t >> 4;                  // fwd: col g == sg, channels c4*4..+3
    int s0 = chunk * 256;

    for (int u = t; u < 2048; u += 256) {
        int K = u >> 6, c = u & 63;
        float v = (K < 16) ? d_Cf[b * 2048 + c * 32 + K]
                           : -d_Cf[b * 2048 + c * 32 + 16 + (K - 16)];
        shA[K][c] = v;
    }
    float w1 = d_gw[b];

    float f00 = 0.f, f01 = 0.f, f10 = 0.f, f11 = 0.f;   // fwd accumulators
    float f20 = 0.f, f21 = 0.f, f30 = 0.f, f31 = 0.f;

    for (int piece = 0; piece < 4; piece++) {
        int sp0 = s0 + piece * 64;
        for (int u = t; u < 512; u += 256) {
            int K = u >> 4, s4 = (u & 15) * 4;
            float4 v;
            if (K < 16) v = *(const float4*)&d_twcT[K * SS + sp0 + s4];
            else        v = *(const float4*)&d_twsT[(K - 16) * SS + sp0 + s4];
            *(float4*)&shT[K][s4] = v;
        }
        __syncthreads();

        // ---- comb GEMM: 4ch x 4s ----
        float acc[4][4];
#pragma unroll
        for (int ci = 0; ci < 4; ci++)
#pragma unroll
            for (int si = 0; si < 4; si++) acc[ci][si] = 0.f;
#pragma unroll
        for (int K = 0; K < 32; K++) {
            float4 a  = *(const float4*)&shA[K][c4 * 4];
            float4 tv = *(const float4*)&shT[K][sg * 4];
            acc[0][0] = fmaf(a.x, tv.x, acc[0][0]); acc[0][1] = fmaf(a.x, tv.y, acc[0][1]);
            acc[0][2] = fmaf(a.x, tv.z, acc[0][2]); acc[0][3] = fmaf(a.x, tv.w, acc[0][3]);
            acc[1][0] = fmaf(a.y, tv.x, acc[1][0]); acc[1][1] = fmaf(a.y, tv.y, acc[1][1]);
            acc[1][2] = fmaf(a.y, tv.z, acc[1][2]); acc[1][3] = fmaf(a.y, tv.w, acc[1][3]);
            acc[2][0] = fmaf(a.z, tv.x, acc[2][0]); acc[2][1] = fmaf(a.z, tv.y, acc[2][1]);
            acc[2][2] = fmaf(a.z, tv.z, acc[2][2]); acc[2][3] = fmaf(a.z, tv.w, acc[2][3]);
            acc[3][0] = fmaf(a.w, tv.x, acc[3][0]); acc[3][1] = fmaf(a.w, tv.y, acc[3][1]);
            acc[3][2] = fmaf(a.w, tv.z, acc[3][2]); acc[3][3] = fmaf(a.w, tv.w, acc[3][3]);
        }

        // ---- epilogue: engram add + exact gelu; stash new h tile in smem ----
        int4 iv = *(const int4*)&d_idx[b * SS + sp0 + sg * 4];
        int ids[4] = {iv.x, iv.y, iv.z, iv.w};
        float ps[4];
#pragma unroll
        for (int si = 0; si < 4; si++) {
            float4 P = *(const float4*)&d_Pall[(layer * NPSP + ids[si]) * HID + c4 * 4];
            float v0 = fmaf(w1, P.x, acc[0][si]);
            float v1 = fmaf(w1, P.y, acc[1][si]);
            float v2 = fmaf(w1, P.z, acc[2][si]);
            float v3 = fmaf(w1, P.w, acc[3][si]);
            float g0 = 0.5f * v0 * (1.f + erff(v0 * 0.70710678118654752f));
            float g1 = 0.5f * v1 * (1.f + erff(v1 * 0.70710678118654752f));
            float g2 = 0.5f * v2 * (1.f + erff(v2 * 0.70710678118654752f));
            float g3 = 0.5f * v3 * (1.f + erff(v3 * 0.70710678118654752f));
            acc[0][si] = g0; acc[1][si] = g1; acc[2][si] = g2; acc[3][si] = g3;
            ps[si] = ((g0 + g1) + g2) + g3;
        }
#pragma unroll
        for (int ci = 0; ci < 4; ci++)
            *(float4*)&sh_h[c4 * 4 + ci][sg * 4] =
                make_float4(acc[ci][0], acc[ci][1], acc[ci][2], acc[ci][3]);
        *(float4*)&shCS[c4 * 64 + sg * 4] = make_float4(ps[0], ps[1], ps[2], ps[3]);
        __syncthreads();

        // channel sums -> d_sC (fixed order)
        if (t < 64) {
            float ss = 0.f;
#pragma unroll
            for (int q = 0; q < 16; q++) ss += shCS[q * 64 + t];
            d_sC[b * SS + sp0 + t] = ss;
        }

        // ---- fwd GEMM on the fresh tile: cols {sg, 16+sg}, channels c4*4..+3 ----
#pragma unroll
        for (int q = 0; q < 16; q++) {
            float4 t0 = *(const float4*)&shT[sg][q * 4];
            float4 t1 = *(const float4*)&shT[sg + 16][q * 4];
            float4 hv;
            hv = *(const float4*)&sh_h[c4 * 4 + 0][q * 4];
            f00 = fmaf(hv.x, t0.x, fmaf(hv.y, t0.y, fmaf(hv.z, t0.z, fmaf(hv.w, t0.w, f00))));
            f01 = fmaf(hv.x, t1.x, fmaf(hv.y, t1.y, fmaf(hv.z, t1.z, fmaf(hv.w, t1.w, f01))));
            hv = *(const float4*)&sh_h[c4 * 4 + 1][q * 4];
            f10 = fmaf(hv.x, t0.x, fmaf(hv.y, t0.y, fmaf(hv.z, t0.z, fmaf(hv.w, t0.w, f10))));
            f11 = fmaf(hv.x, t1.x, fmaf(hv.y, t1.y, fmaf(hv.z, t1.z, fmaf(hv.w, t1.w, f11))));
            hv = *(const float4*)&sh_h[c4 * 4 + 2][q * 4];
            f20 = fmaf(hv.x, t0.x, fmaf(hv.y, t0.y, fmaf(hv.z, t0.z, fmaf(hv.w, t0.w, f20))));
            f21 = fmaf(hv.x, t1.x, fmaf(hv.y, t1.y, fmaf(hv.z, t1.z, fmaf(hv.w, t1.w, f21))));
            hv = *(const float4*)&sh_h[c4 * 4 + 3][q * 4];
            f30 = fmaf(hv.x, t0.x, fmaf(hv.y, t0.y, fmaf(hv.z, t0.z, fmaf(hv.w, t0.w, f30))));
            f31 = fmaf(hv.x, t1.x, fmaf(hv.y, t1.y, fmaf(hv.z, t1.z, fmaf(hv.w, t1.w, f31))));
        }
        __syncthreads();
    }
    float* p = &d_part[((size_t)(b * NCH + chunk) * HID + c4 * 4) * 32];
    p[0 * 32 + sg] = f00;  p[0 * 32 + 16 + sg] = f01;
    p[1 * 32 + sg] = f10;  p[1 * 32 + 16 + sg] = f11;
    p[2 * 32 + sg] = f20;  p[2 * 32 + 16 + sg] = f21;
    p[3 * 32 + sg] = f30;  p[3 * 32 + 16 + sg] = f31;
}

// ---------------- final combine: comb(NL-1) fused with output projection ----------------
__global__ void __launch_bounds__(256) k_comb_last(const float* __restrict__ projW,
                                                   const float* __restrict__ projb,
                                                   float* __restrict__ out) {
    const int layer = NL - 1;
    __shared__ float shA[32][68];
    __shared__ float shT[32][68];
    __shared__ float shCS[16 * 64];
    int b = blockIdx.y, chunk = blockIdx.x, t = threadIdx.x;
    int sg = t & 15, c4 = t >> 4;
    int s0 = chunk * 256;

    for (int u = t; u < 2048; u += 256) {
        int K = u >> 6, c = u & 63;
        float v = (K < 16) ? d_Cf[b * 2048 + c * 32 + K]
                           : -d_Cf[b * 2048 + c * 32 + 16 + (K - 16)];
        shA[K][c] = v;
    }
    float w1 = d_gw[b];
    float pw0 = __ldg(&projW[c4 * 4 + 0]);
    float pw1 = __ldg(&projW[c4 * 4 + 1]);
    float pw2 = __ldg(&projW[c4 * 4 + 2]);
    float pw3 = __ldg(&projW[c4 * 4 + 3]);

    for (int piece = 0; piece < 4; piece++) {
        int sp0 = s0 + piece * 64;
        for (int u = t; u < 512; u += 256) {
            int K = u >> 4, s4 = (u & 15) * 4;
            float4 v;
            if (K < 16) v = *(const float4*)&d_twcT[K * SS + sp0 + s4];
            else        v = *(const float4*)&d_twsT[(K - 16) * SS + sp0 + s4];
            *(float4*)&shT[K][s4] = v;
        }
        __syncthreads();

        float acc[4][4];
#pragma unroll
        for (int ci = 0; ci < 4; ci++)
#pragma unroll
            for (int si = 0; si < 4; si++) acc[ci][si] = 0.f;
#pragma unroll
        for (int K = 0; K < 32; K++) {
            float4 a  = *(const float4*)&shA[K][c4 * 4];
            float4 tv = *(const float4*)&shT[K][sg * 4];
            acc[0][0] = fmaf(a.x, tv.x, acc[0][0]); acc[0][1] = fmaf(a.x, tv.y, acc[0][1]);
            acc[0][2] = fmaf(a.x, tv.z, acc[0][2]); acc[0][3] = fmaf(a.x, tv.w, acc[0][3]);
            acc[1][0] = fmaf(a.y, tv.x, acc[1][0]); acc[1][1] = fmaf(a.y, tv.y, acc[1][1]);
            acc[1][2] = fmaf(a.y, tv.z, acc[1][2]); acc[1][3] = fmaf(a.y, tv.w, acc[1][3]);
            acc[2][0] = fmaf(a.z, tv.x, acc[2][0]); acc[2][1] = fmaf(a.z, tv.y, acc[2][1]);
            acc[2][2] = fmaf(a.z, tv.z, acc[2][2]); acc[2][3] = fmaf(a.z, tv.w, acc[2][3]);
            acc[3][0] = fmaf(a.w, tv.x, acc[3][0]); acc[3][1] = fmaf(a.w, tv.y, acc[3][1]);
            acc[3][2] = fmaf(a.w, tv.z, acc[3][2]); acc[3][3] = fmaf(a.w, tv.w, acc[3][3]);
        }

        int4 iv = *(const int4*)&d_idx[b * SS + sp0 + sg * 4];
        int ids[4] = {iv.x, iv.y, iv.z, iv.w};
        float ps[4];
#pragma unroll
        for (int si = 0; si < 4; si++) {
            float4 P = *(const float4*)&d_Pall[(layer * NPSP + ids[si]) * HID + c4 * 4];
            float v0 = fmaf(w1, P.x, acc[0][si]);
            float v1 = fmaf(w1, P.y, acc[1][si]);
            float v2 = fmaf(w1, P.z, acc[2][si]);
            float v3 = fmaf(w1, P.w, acc[3][si]);
            float g0 = 0.5f * v0 * (1.f + erff(v0 * 0.70710678118654752f));
            float g1 = 0.5f * v1 * (1.f + erff(v1 * 0.70710678118654752f));
            float g2 = 0.5f * v2 * (1.f + erff(v2 * 0.70710678118654752f));
            float g3 = 0.5f * v3 * (1.f + erff(v3 * 0.70710678118654752f));
            ps[si] = fmaf(g0, pw0, fmaf(g1, pw1, fmaf(g2, pw2, g3 * pw3)));
        }
        *(float4*)&shCS[c4 * 64 + sg * 4] = make_float4(ps[0], ps[1], ps[2], ps[3]);
        __syncthreads();
        if (t < 64) {
            float ss = 0.f;
#pragma unroll
            for (int q = 0; q < 16; q++) ss += shCS[q * 64 + t];
            out[b * SS + sp0 + t] = ss + projb[0];
        }
        __syncthreads();
    }
}

// ---------------- host ----------------
extern "C" void kernel_launch(void* const* d_in, const int* in_sizes, int n_in,
                              void* d_out, int out_size) {
    const float* x      = (const float*)d_in[0];
    const float* lift_W = (const float*)d_in[1];
    const float* lift_b = (const float*)d_in[2];
    const float* proj_W = (const float*)d_in[3];
    const float* proj_b = (const float*)d_in[4];
    const float* sp_emb = (const float*)d_in[5];
    const float* sp_W   = (const float*)d_in[6];
    const float* sp_b   = (const float*)d_in[7];
    const float* fr_emb = (const float*)d_in[8];
    const float* fr_W   = (const float*)d_in[9];
    const float* fr_b   = (const float*)d_in[10];
    const float* gW1    = (const float*)d_in[11];
    const float* gb1    = (const float*)d_in[12];
    const float* gW2    = (const float*)d_in[13];
    const float* gb2    = (const float*)d_in[14];
    const float* mhf_Wr = (const float*)d_in[15];
    const float* mhf_Wi = (const float*)d_in[16];
    float* out = (float*)d_out;

    k_init_tw<<<(SS * NM) / 256, 256>>>();
    k_prep_all<<<(NL * NPSP * HID + 255) / 256, 256>>>(sp_emb, sp_W, sp_b);
    k_lift<<<(BB * SS) / 256, 256>>>(x, lift_W, lift_b);

    // layer 0: forward DFT (+hash of lifted h), reduce, mix
    k_fwd1<<<dim3(NCH, BB), 256>>>();
    k_fwd2<<<(BB * HID * 32) / 256, 256>>>();
    k_mix<<<BB, 256>>>(fr_emb, fr_W, fr_b, mhf_Wr, mhf_Wi, gW1, gb1, gW2, gb2, 0);

    // transitions: fused comb(l-1)+fwd(l), then hash, reduce, mix(l)
    for (int l = 1; l < NL; l++) {
        k_fused<<<dim3(NCH, BB), 256>>>(l - 1);
        k_hash<<<dim3(NCH, BB), 256>>>();
        k_fwd2<<<(BB * HID * 32) / 256, 256>>>();
        k_mix<<<BB, 256>>>(fr_emb, fr_W, fr_b, mhf_Wr, mhf_Wi, gW1, gb1, gW2, gb2, l);
    }

    // final combine + projection
    k_comb_last<<<dim3(NCH, BB), 256>>>(proj_W, proj_b, out);
}

// round 13
// speedup vs baseline: 1.6389x; 1.1016x over previous
#include <cuda_runtime.h>
#include <cuda_bf16.h>
#include <math.h>

#define BB   16
#define CIN  3
#define SS   16384
#define SH   8192        // SS/2 (half-wave pairing)
#define HID  64
#define NM   16
#define NL   4
#define NPSP 500
#define NPFR 200
#define ED   8
#define NCH  32          // paired chunks (256 pairs = 512 samples each)

// ---------------- scratch (__device__ globals; no allocation) ----------------
__device__ float d_hA[BB * HID * SS];            // 64 MB (layer-0 h only)
__device__ float d_twcT[NM * SH];                // [k][s] cos, s < 8192
__device__ float d_twsT[NM * SH];                // [k][s] sin
__device__ float d_part[BB * NCH * HID * 32];    // split-K partials, 4 MB
__device__ float d_Xf[BB * HID * 32];            // reduced spectrum
__device__ float d_Cf[BB * HID * 32];            // combined scaled spectrum: 0..15 Re', 16..31 Im'
__device__ float d_sC[BB * SS];                  // per-position channel sums (for spatial hash)
__device__ int   d_idx[BB * SS];                 // spatial hash index
__device__ int   d_cnt[BB * NPSP];               // per-batch global histogram
__device__ float d_Pall[NL * NPSP * HID];        // projected spatial patterns, all layers
__device__ float d_gw[BB];                       // gate weight w1 per batch

// ---------------- twiddles (float sinpi/cospi; args 2m/S exact in fp32) ----------------
__global__ void k_init_tw() {
    int i = blockIdx.x * 256 + threadIdx.x;        // i < NM*SH
    int k = i >> 13, s = i & (SH - 1);
    int m = (s * k) & (SS - 1);
    float x = (float)(2 * m) / (float)SS;
    d_twcT[i] = cospif(x);
    d_twsT[i] = sinpif(x);
}

// ---------------- all-layer spatial pattern projection + initial d_cnt zero ----------------
__global__ void k_prep_all(const float* __restrict__ sp_emb, const float* __restrict__ sp_W,
                           const float* __restrict__ sp_b) {
    int i = blockIdx.x * 256 + threadIdx.x;        // NL*NPSP*HID = 128000
    if (i < BB * NPSP) d_cnt[i] = 0;
    if (i >= NL * NPSP * HID) return;
    int l = i / (NPSP * HID);
    int r = i - l * (NPSP * HID);
    int p = r / HID, c = r % HID;
    const float* e = sp_emb + (l * NPSP + p) * ED;
    const float* W = sp_W + l * ED * HID;
    float acc = sp_b[l * HID + c];
#pragma unroll
    for (int j = 0; j < ED; j++) acc = fmaf(e[j], W[j * HID + c], acc);
    d_Pall[i] = acc;
}

// ---------------- lift: h0 = x @ lift_W + lift_b  (+ channel sums for hash) ----------------
__global__ void k_lift(const float* __restrict__ x, const float* __restrict__ W,
                       const float* __restrict__ bias) {
    int i = blockIdx.x * 256 + threadIdx.x;        // over B*S
    int b = i >> 14;
    int s = i & (SS - 1);
    float x0 = x[(b * CIN + 0) * SS + s];
    float x1 = x[(b * CIN + 1) * SS + s];
    float x2 = x[(b * CIN + 2) * SS + s];
    float csum = 0.f;
#pragma unroll
    for (int c = 0; c < HID; c++) {
        float v = fmaf(x0, __ldg(&W[0 * HID + c]),
                  fmaf(x1, __ldg(&W[1 * HID + c]),
                  fmaf(x2, __ldg(&W[2 * HID + c]), __ldg(&bias[c]))));
        d_hA[(b * HID + c) * SS + s] = v;
        csum += v;
    }
    d_sC[b * SS + s] = csum;
}

// ---------------- layer-0 forward DFT (paired half-wave; reads d_hA) ----------------
// grid (NCH=32, B). Block: 256 pairs (s, s+8192) in 8 pieces of 32 pairs.
// Thread: g = t&15 -> cols {g, 16+g}; c4 = t>>4 -> channels {4c4..+3}.
// Even-g cols consume hp = h1+h2, odd-g consume hm = h1-h2 -> FLOPs halved.
__global__ void __launch_bounds__(256) k_fwd1() {
    __shared__ float sh_hp[64][36];
    __shared__ float sh_hm[64][36];
    __shared__ float shT[32][36];
    int chunk = blockIdx.x, b = blockIdx.y, t = threadIdx.x;
    int g = t & 15, c4 = t >> 4;
    int ps0 = chunk * 256;

    float f[4][2];
#pragma unroll
    for (int ci = 0; ci < 4; ci++) { f[ci][0] = 0.f; f[ci][1] = 0.f; }

    for (int piece = 0; piece < 8; piece++) {
        int pp0 = ps0 + piece * 32;
        for (int u = t; u < 512; u += 256) {
            int cc = u >> 3, j4 = (u & 7) * 4;
            float4 v1 = *(const float4*)&d_hA[(b * HID + cc) * SS + pp0 + j4];
            float4 v2 = *(const float4*)&d_hA[(b * HID + cc) * SS + SH + pp0 + j4];
            *(float4*)&sh_hp[cc][j4] = make_float4(v1.x + v2.x, v1.y + v2.y, v1.z + v2.z, v1.w + v2.w);
            *(float4*)&sh_hm[cc][j4] = make_float4(v1.x - v2.x, v1.y - v2.y, v1.z - v2.z, v1.w - v2.w);
        }
        {
            int u = t;                             // 256 float4 = exactly 1 per thread
            int col = u >> 3, j4 = (u & 7) * 4;
            float4 v;
            if (col < 16) v = *(const float4*)&d_twcT[col * SH + pp0 + j4];
            else          v = *(const float4*)&d_twsT[(col - 16) * SH + pp0 + j4];
            *(float4*)&shT[col][j4] = v;
        }
        __syncthreads();
        const float (*hb)[36] = (g & 1) ? (const float (*)[36])sh_hm : (const float (*)[36])sh_hp;
#pragma unroll
        for (int q = 0; q < 8; q++) {
            float4 t0 = *(const float4*)&shT[g][q * 4];
            float4 t1 = *(const float4*)&shT[g + 16][q * 4];
#pragma unroll
            for (int ci = 0; ci < 4; ci++) {
                float4 hv = *(const float4*)&hb[c4 * 4 + ci][q * 4];
                f[ci][0] = fmaf(hv.x, t0.x, fmaf(hv.y, t0.y, fmaf(hv.z, t0.z, fmaf(hv.w, t0.w, f[ci][0]))));
                f[ci][1] = fmaf(hv.x, t1.x, fmaf(hv.y, t1.y, fmaf(hv.z, t1.z, fmaf(hv.w, t1.w, f[ci][1]))));
            }
        }
        __syncthreads();
    }
    float* p = &d_part[((size_t)(b * NCH + chunk) * HID + c4 * 4) * 32];
#pragma unroll
    for (int ci = 0; ci < 4; ci++) {
        p[ci * 32 + g]      = f[ci][0];
        p[ci * 32 + 16 + g] = f[ci][1];
    }
}

// ---------------- aux: spectrum reduce (chunk<8) + spatial hash + histogram ----------------
__global__ void __launch_bounds__(256) k_aux() {
    __shared__ int hist[NPSP];
    int b = blockIdx.y, chunk = blockIdx.x, t = threadIdx.x;
    for (int i = t; i < NPSP; i += 256) hist[i] = 0;

    if (chunk < 8) {                               // 8x16 blocks x 256 t = 32768 entries
        int u = chunk * 256 + t;
        const float* p = d_part + (size_t)b * NCH * 2048 + u;
        double acc = 0.0;
#pragma unroll 8
        for (int ch = 0; ch < NCH; ch++) acc += (double)p[(size_t)ch * 2048];
        d_Xf[b * 2048 + u] = (float)acc;
    }
    __syncthreads();

    int s = chunk * 256 + t;
    const float* sc = d_sC + b * SS;
    int a0 = max(s - 2, 0), a1 = max(s - 1, 0), a3 = min(s + 1, SS - 1);
    float w = ((sc[a0] + sc[a1]) + sc[s]) + sc[a3];
    int iv = (int)(w * 31.0f);
    int m = iv % NPSP; if (m < 0) m += NPSP;
    d_idx[b * SS + s] = m;
    atomicAdd(&hist[m], 1);
    __syncthreads();
    for (int i = t; i < NPSP; i += 256)
        if (hist[i]) atomicAdd(&d_cnt[b * NPSP + i], hist[i]);
}

// ---------------- per-batch: spectral mix + gate + combined spectrum ----------------
__global__ void __launch_bounds__(256) k_mix(
        const float* __restrict__ fr_emb, const float* __restrict__ fr_W,
        const float* __restrict__ fr_b,
        const float* __restrict__ mhf_Wr, const float* __restrict__ mhf_Wi,
        const float* __restrict__ gW1, const float* __restrict__ gb1,
        const float* __restrict__ gW2, const float* __restrict__ gb2,
        int layer) {
    __shared__ float shX[HID * 32];
    __shared__ float shMHre[HID * NM];
    __shared__ float shMHim[HID * NM];
    __shared__ float shFR[HID * NM];
    __shared__ double shmagp[4][16];
    __shared__ double shgp[4][64];
    __shared__ float shg[192];
    __shared__ float shhid[64];
    __shared__ float shw[3];
    __shared__ int   shmi[16];
    __shared__ int   sh_ifr;
    int b = blockIdx.x, t = threadIdx.x;

    for (int i = t; i < HID * 32; i += 256) shX[i] = d_Xf[b * HID * 32 + i];
    __syncthreads();

    // spectral magnitude hash: 4 fixed-order fp64 slices of 16 channels
    if (t < 64) {
        int k = t & 15, sl = t >> 4;
        double acc = 0.0;
        for (int c = sl * 16; c < sl * 16 + 16; c++) {
            double re = (double)shX[c * 32 + k];
            double im = (double)shX[c * 32 + 16 + k];
            acc += sqrt(re * re + im * im);
        }
        shmagp[sl][k] = acc;
    }
    // multi-head Fourier mix
    for (int u = t; u < 1024; u += 256) {            // u = h*256 + o*16 + k
        int h_ = u >> 8, o = (u >> 4) & 15, k = u & 15;
        float ar = 0.f, ai = 0.f;
        const float* Wr = mhf_Wr + (((layer * 4 + h_) * 16) * 16 + o) * 16 + k;
        const float* Wi = mhf_Wi + (((layer * 4 + h_) * 16) * 16 + o) * 16 + k;
#pragma unroll
        for (int i = 0; i < 16; i++) {
            int cin = h_ * 16 + i;
            float re = shX[cin * 32 + k];
            float im = -shX[cin * 32 + 16 + k];
            float wr = Wr[i * 256];
            float wi = Wi[i * 256];
            ar = fmaf(re, wr, ar); ar = fmaf(-im, wi, ar);
            ai = fmaf(re, wi, ai); ai = fmaf(im, wr, ai);
        }
        int cout = h_ * 16 + o;
        shMHre[cout * 16 + k] = ar;
        shMHim[cout * 16 + k] = ai;
    }
    __syncthreads();
    if (t < 16) {
        double acc = ((shmagp[0][t] + shmagp[1][t]) + shmagp[2][t]) + shmagp[3][t];
        float mag = (float)(acc / 64.0);
        shmi[t] = (int)(mag * 1000.0f);
    }
    __syncthreads();
    if (t == 0) {
        int ssum = 0;
        for (int k = 0; k < 16; k++) ssum += shmi[k];
        int m = ssum % NPFR; if (m < 0) m += NPFR;
        sh_ifr = m;
    }
    __syncthreads();
    // spectral engram projection
    {
        const float* e = fr_emb + (layer * NPFR + sh_ifr) * ED;
        for (int u = t; u < 1024; u += 256) {        // u = c*16+k
            const float* W = fr_W + layer * ED * 1024 + u;
            float acc = fr_b[layer * 1024 + u];
#pragma unroll
            for (int j = 0; j < ED; j++) acc = fmaf(e[j], W[j * 1024], acc);
            shFR[u] = acc;
        }
    }
    // gate spatial mean: 4 fixed-order fp64 slices of 125 patterns
    {
        int c = t & 63, sl = t >> 6;
        double acc = 0.0;
        const float* P = d_Pall + layer * NPSP * HID;
        const int* cnt = d_cnt + b * NPSP;
        for (int p = sl * 125; p < sl * 125 + 125; p++)
            acc += (double)cnt[p] * (double)P[p * HID + c];
        shgp[sl][c] = acc;
    }
    __syncthreads();
    // all d_cnt reads complete -> zero it for the next layer's hash
    for (int i = t; i < NPSP; i += 256) d_cnt[b * NPSP + i] = 0;
    if (t < 64) {
        double acc = ((shgp[0][t] + shgp[1][t]) + shgp[2][t]) + shgp[3][t];
        shg[t]       = (float)(acc / (double)SS);
        shg[64 + t]  = shMHre[t * 16 + 0] / (float)SS;
        shg[128 + t] = shFR[t * 16 + 0] / (float)SS;
    }
    __syncthreads();
    if (t < 64) {
        float acc = gb1[layer * 64 + t];
        const float* W1 = gW1 + layer * 192 * 64;
        for (int j = 0; j < 192; j++) acc = fmaf(shg[j], W1[j * 64 + t], acc);
        shhid[t] = fmaxf(acc, 0.f);
    }
    __syncthreads();
    if (t == 0) {
        float lg[3];
        const float* W2 = gW2 + layer * 64 * 3;
        for (int o = 0; o < 3; o++) {
            float acc = gb2[layer * 3 + o];
            for (int j = 0; j < 64; j++) acc = fmaf(shhid[j], W2[j * 3 + o], acc);
            lg[o] = acc;
        }
        float mx = fmaxf(lg[0], fmaxf(lg[1], lg[2]));
        float e0 = expf(lg[0] - mx), e1 = expf(lg[1] - mx), e2 = expf(lg[2] - mx);
        float inv = 1.f / (e0 + e1 + e2);
        shw[0] = e0 * inv; shw[1] = e1 * inv; shw[2] = e2 * inv;
        d_gw[b] = shw[0];
    }
    __syncthreads();
    // combined, irfft-prescaled spectrum
    float w2 = shw[1], w3 = shw[2];
    for (int u = t; u < 1024; u += 256) {            // u = c*16+k
        int k = u & 15;
        int c = u >> 4;
        float sc = ((k == 0) ? 1.f : 2.f) / (float)SS;
        d_Cf[(b * HID + c) * 32 + k]      = (w2 * shMHre[u] + w3 * shFR[u]) * sc;
        d_Cf[(b * HID + c) * 32 + 16 + k] = (w2 * shMHim[u]) * sc;
    }
}

// ---------------- fused transition (paired): comb(layer) -> gelu -> fwd partials ----------------
// comb: E = sum_{K even} A[K][c]T[K][s], O = sum_{K odd}; h(s)=E+O, h(s+SH)=E-O. gelu both.
// Then hp=g1+g2, hm=g1-g2 -> fwd cols even/odd consume hp/hm. h never hits global.
__global__ void __launch_bounds__(256) k_fused(int layer) {
    __shared__ float shA[32][68];                  // [K][channel]
    __shared__ float shT[32][36];                  // [K][pair s_local]
    __shared__ float sh_hp[64][36];
    __shared__ float sh_hm[64][36];
    __shared__ float shCS[16][68];                 // per-c4 channel sums, 64 sample cols
    int b = blockIdx.y, chunk = blockIdx.x, t = threadIdx.x;
    int g = t & 15, c4 = t >> 4;
    int ps0 = chunk * 256;

    for (int u = t; u < 2048; u += 256) {
        int K = u >> 6, c = u & 63;
        float v = (K < 16) ? d_Cf[b * 2048 + c * 32 + K]
                           : -d_Cf[b * 2048 + c * 32 + 16 + (K - 16)];
        shA[K][c] = v;
    }
    float w1 = d_gw[b];

    float f[4][2];
#pragma unroll
    for (int ci = 0; ci < 4; ci++) { f[ci][0] = 0.f; f[ci][1] = 0.f; }

    for (int piece = 0; piece < 8; piece++) {
        int pp0 = ps0 + piece * 32;
        {
            int u = t;
            int col = u >> 3, j4 = (u & 7) * 4;
            float4 v;
            if (col < 16) v = *(const float4*)&d_twcT[col * SH + pp0 + j4];
            else          v = *(const float4*)&d_twsT[(col - 16) * SH + pp0 + j4];
            *(float4*)&shT[col][j4] = v;
        }
        __syncthreads();

        // ---- comb GEMM: even/odd-K accumulation, 4ch x 2 pairs ----
        float aE[4][2], aO[4][2];
#pragma unroll
        for (int ci = 0; ci < 4; ci++) { aE[ci][0] = aE[ci][1] = 0.f; aO[ci][0] = aO[ci][1] = 0.f; }
#pragma unroll
        for (int K = 0; K < 32; K += 2) {
            {
                float4 a  = *(const float4*)&shA[K][c4 * 4];
                float2 tv = *(const float2*)&shT[K][g * 2];
                aE[0][0] = fmaf(a.x, tv.x, aE[0][0]); aE[0][1] = fmaf(a.x, tv.y, aE[0][1]);
                aE[1][0] = fmaf(a.y, tv.x, aE[1][0]); aE[1][1] = fmaf(a.y, tv.y, aE[1][1]);
                aE[2][0] = fmaf(a.z, tv.x, aE[2][0]); aE[2][1] = fmaf(a.z, tv.y, aE[2][1]);
                aE[3][0] = fmaf(a.w, tv.x, aE[3][0]); aE[3][1] = fmaf(a.w, tv.y, aE[3][1]);
            }
            {
                float4 a  = *(const float4*)&shA[K + 1][c4 * 4];
                float2 tv = *(const float2*)&shT[K + 1][g * 2];
                aO[0][0] = fmaf(a.x, tv.x, aO[0][0]); aO[0][1] = fmaf(a.x, tv.y, aO[0][1]);
                aO[1][0] = fmaf(a.y, tv.x, aO[1][0]); aO[1][1] = fmaf(a.y, tv.y, aO[1][1]);
                aO[2][0] = fmaf(a.z, tv.x, aO[2][0]); aO[2][1] = fmaf(a.z, tv.y, aO[2][1]);
                aO[3][0] = fmaf(a.w, tv.x, aO[3][0]); aO[3][1] = fmaf(a.w, tv.y, aO[3][1]);
            }
        }

        // ---- epilogue: engram + exact gelu for both halves; stash hp/hm ----
        int2 i1 = *(const int2*)&d_idx[b * SS + pp0 + g * 2];
        int2 i2 = *(const int2*)&d_idx[b * SS + SH + pp0 + g * 2];
        int idx1[2] = {i1.x, i1.y};
        int idx2[2] = {i2.x, i2.y};
#pragma unroll
        for (int pr = 0; pr < 2; pr++) {
            float4 P1 = *(const float4*)&d_Pall[(layer * NPSP + idx1[pr]) * HID + c4 * 4];
            float4 P2 = *(const float4*)&d_Pall[(layer * NPSP + idx2[pr]) * HID + c4 * 4];
            float pv1[4] = {P1.x, P1.y, P1.z, P1.w};
            float pv2[4] = {P2.x, P2.y, P2.z, P2.w};
            float cs1 = 0.f, cs2 = 0.f;
#pragma unroll
            for (int ci = 0; ci < 4; ci++) {
                float h1 = aE[ci][pr] + aO[ci][pr];
                float h2 = aE[ci][pr] - aO[ci][pr];
                float v1 = fmaf(w1, pv1[ci], h1);
                float v2 = fmaf(w1, pv2[ci], h2);
                float g1 = 0.5f * v1 * (1.f + erff(v1 * 0.70710678118654752f));
                float g2 = 0.5f * v2 * (1.f + erff(v2 * 0.70710678118654752f));
                sh_hp[c4 * 4 + ci][g * 2 + pr] = g1 + g2;
                sh_hm[c4 * 4 + ci][g * 2 + pr] = g1 - g2;
                cs1 += g1; cs2 += g2;
            }
            shCS[c4][g * 2 + pr]      = cs1;
            shCS[c4][32 + g * 2 + pr] = cs2;
        }
        __syncthreads();

        if (t < 64) {
            float ss = 0.f;
#pragma unroll
            for (int q = 0; q < 16; q++) ss += shCS[q][t];   // fixed order
            if (t < 32) d_sC[b * SS + pp0 + t] = ss;
            else        d_sC[b * SS + SH + pp0 + t - 32] = ss;
        }

        // ---- fwd GEMM on fresh tile: cols {g, 16+g}, parity selects hp/hm ----
        const float (*hb)[36] = (g & 1) ? (const float (*)[36])sh_hm : (const float (*)[36])sh_hp;
#pragma unroll
        for (int q = 0; q < 8; q++) {
            float4 t0 = *(const float4*)&shT[g][q * 4];
            float4 t1 = *(const float4*)&shT[g + 16][q * 4];
#pragma unroll
            for (int ci = 0; ci < 4; ci++) {
                float4 hv = *(const float4*)&hb[c4 * 4 + ci][q * 4];
                f[ci][0] = fmaf(hv.x, t0.x, fmaf(hv.y, t0.y, fmaf(hv.z, t0.z, fmaf(hv.w, t0.w, f[ci][0]))));
                f[ci][1] = fmaf(hv.x, t1.x, fmaf(hv.y, t1.y, fmaf(hv.z, t1.z, fmaf(hv.w, t1.w, f[ci][1]))));
            }
        }
        __syncthreads();
    }
    float* p = &d_part[((size_t)(b * NCH + chunk) * HID + c4 * 4) * 32];
#pragma unroll
    for (int ci = 0; ci < 4; ci++) {
        p[ci * 32 + g]      = f[ci][0];
        p[ci * 32 + 16 + g] = f[ci][1];
    }
}

// ---------------- final combine (paired) + output projection ----------------
__global__ void __launch_bounds__(256) k_comb_last(const float* __restrict__ projW,
                                                   const float* __restrict__ projb,
                                                   float* __restrict__ out) {
    const int layer = NL - 1;
    __shared__ float shA[32][68];
    __shared__ float shT[32][36];
    __shared__ float shCS[16][68];
    int b = blockIdx.y, chunk = blockIdx.x, t = threadIdx.x;
    int g = t & 15, c4 = t >> 4;
    int ps0 = chunk * 256;

    for (int u = t; u < 2048; u += 256) {
        int K = u >> 6, c = u & 63;
        float v = (K < 16) ? d_Cf[b * 2048 + c * 32 + K]
                           : -d_Cf[b * 2048 + c * 32 + 16 + (K - 16)];
        shA[K][c] = v;
    }
    float w1 = d_gw[b];
    float4 PW = *(const float4*)&projW[c4 * 4];
    float pw[4] = {PW.x, PW.y, PW.z, PW.w};

    for (int piece = 0; piece < 8; piece++) {
        int pp0 = ps0 + piece * 32;
        {
            int u = t;
            int col = u >> 3, j4 = (u & 7) * 4;
            float4 v;
            if (col < 16) v = *(const float4*)&d_twcT[col * SH + pp0 + j4];
            else          v = *(const float4*)&d_twsT[(col - 16) * SH + pp0 + j4];
            *(float4*)&shT[col][j4] = v;
        }
        __syncthreads();

        float aE[4][2], aO[4][2];
#pragma unroll
        for (int ci = 0; ci < 4; ci++) { aE[ci][0] = aE[ci][1] = 0.f; aO[ci][0] = aO[ci][1] = 0.f; }
#pragma unroll
        for (int K = 0; K < 32; K += 2) {
            {
                float4 a  = *(const float4*)&shA[K][c4 * 4];
                float2 tv = *(const float2*)&shT[K][g * 2];
                aE[0][0] = fmaf(a.x, tv.x, aE[0][0]); aE[0][1] = fmaf(a.x, tv.y, aE[0][1]);
                aE[1][0] = fmaf(a.y, tv.x, aE[1][0]); aE[1][1] = fmaf(a.y, tv.y, aE[1][1]);
                aE[2][0] = fmaf(a.z, tv.x, aE[2][0]); aE[2][1] = fmaf(a.z, tv.y, aE[2][1]);
                aE[3][0] = fmaf(a.w, tv.x, aE[3][0]); aE[3][1] = fmaf(a.w, tv.y, aE[3][1]);
            }
            {
                float4 a  = *(const float4*)&shA[K + 1][c4 * 4];
                float2 tv = *(const float2*)&shT[K + 1][g * 2];
                aO[0][0] = fmaf(a.x, tv.x, aO[0][0]); aO[0][1] = fmaf(a.x, tv.y, aO[0][1]);
                aO[1][0] = fmaf(a.y, tv.x, aO[1][0]); aO[1][1] = fmaf(a.y, tv.y, aO[1][1]);
                aO[2][0] = fmaf(a.z, tv.x, aO[2][0]); aO[2][1] = fmaf(a.z, tv.y, aO[2][1]);
                aO[3][0] = fmaf(a.w, tv.x, aO[3][0]); aO[3][1] = fmaf(a.w, tv.y, aO[3][1]);
            }
        }

        int2 i1 = *(const int2*)&d_idx[b * SS + pp0 + g * 2];
        int2 i2 = *(const int2*)&d_idx[b * SS + SH + pp0 + g * 2];
        int idx1[2] = {i1.x, i1.y};
        int idx2[2] = {i2.x, i2.y};
#pragma unroll
        for (int pr = 0; pr < 2; pr++) {
            float4 P1 = *(const float4*)&d_Pall[(layer * NPSP + idx1[pr]) * HID + c4 * 4];
            float4 P2 = *(const float4*)&d_Pall[(layer * NPSP + idx2[pr]) * HID + c4 * 4];
            float pv1[4] = {P1.x, P1.y, P1.z, P1.w};
            float pv2[4] = {P2.x, P2.y, P2.z, P2.w};
            float ps1 = 0.f, ps2 = 0.f;
#pragma unroll
            for (int ci = 0; ci < 4; ci++) {
                float h1 = aE[ci][pr] + aO[ci][pr];
                float h2 = aE[ci][pr] - aO[ci][pr];
                float v1 = fmaf(w1, pv1[ci], h1);
                float v2 = fmaf(w1, pv2[ci], h2);
                float g1 = 0.5f * v1 * (1.f + erff(v1 * 0.70710678118654752f));
                float g2 = 0.5f * v2 * (1.f + erff(v2 * 0.70710678118654752f));
                ps1 = fmaf(g1, pw[ci], ps1);
                ps2 = fmaf(g2, pw[ci], ps2);
            }
            shCS[c4][g * 2 + pr]      = ps1;
            shCS[c4][32 + g * 2 + pr] = ps2;
        }
        __syncthreads();
        if (t < 64) {
            float ss = 0.f;
#pragma unroll
            for (int q = 0; q < 16; q++) ss += shCS[q][t];
            if (t < 32) out[b * SS + pp0 + t] = ss + projb[0];
            else        out[b * SS + SH + pp0 + t - 32] = ss + projb[0];
        }
        __syncthreads();
    }
}

// ---------------- host ----------------
extern "C" void kernel_launch(void* const* d_in, const int* in_sizes, int n_in,
                              void* d_out, int out_size) {
    const float* x      = (const float*)d_in[0];
    const float* lift_W = (const float*)d_in[1];
    const float* lift_b = (const float*)d_in[2];
    const float* proj_W = (const float*)d_in[3];
    const float* proj_b = (const float*)d_in[4];
    const float* sp_emb = (const float*)d_in[5];
    const float* sp_W   = (const float*)d_in[6];
    const float* sp_b   = (const float*)d_in[7];
    const float* fr_emb = (const float*)d_in[8];
    const float* fr_W   = (const float*)d_in[9];
    const float* fr_b   = (const float*)d_in[10];
    const float* gW1    = (const float*)d_in[11];
    const float* gb1    = (const float*)d_in[12];
    const float* gW2    = (const float*)d_in[13];
    const float* gb2    = (const float*)d_in[14];
    const float* mhf_Wr = (const float*)d_in[15];
    const float* mhf_Wi = (const float*)d_in[16];
    float* out = (float*)d_out;

    k_init_tw<<<(NM * SH) / 256, 256>>>();
    k_prep_all<<<(NL * NPSP * HID + 255) / 256, 256>>>(sp_emb, sp_W, sp_b);
    k_lift<<<(BB * SS) / 256, 256>>>(x, lift_W, lift_b);

    for (int l = 0; l < NL; l++) {
        if (l == 0) k_fwd1<<<dim3(NCH, BB), 256>>>();
        else        k_fused<<<dim3(NCH, BB), 256>>>(l - 1);
        k_aux<<<dim3(64, BB), 256>>>();
        k_mix<<<BB, 256>>>(fr_emb, fr_W, fr_b, mhf_Wr, mhf_Wi, gW1, gb1, gW2, gb2, l);
    }
    k_comb_last<<<dim3(NCH, BB), 256>>>(proj_W, proj_b, out);
}

// round 14
// speedup vs baseline: 1.7533x; 1.0698x over previous
#include <cuda_runtime.h>
#include <cuda_bf16.h>
#include <math.h>

#define BB   16
#define CIN  3
#define SS   16384
#define SH   8192        // SS/2 (half-wave pairing)
#define HID  64
#define NM   16
#define NL   4
#define NPSP 500
#define NPFR 200
#define ED   8
#define NCH  32          // paired chunks (256 pairs = 512 samples each)

// ---------------- scratch (__device__ globals; no allocation) ----------------
__device__ float d_twcT[NM * SH];                // [k][s] cos, s < 8192
__device__ float d_twsT[NM * SH];                // [k][s] sin
__device__ float d_part[BB * NCH * HID * 32];    // split-K partials, 4 MB
__device__ float d_Xf[BB * HID * 32];            // reduced spectrum
__device__ float d_Cf[BB * HID * 32];            // combined scaled spectrum: 0..15 Re', 16..31 Im'
__device__ float d_sC[BB * SS];                  // per-position channel sums (for spatial hash)
__device__ int   d_idx[BB * SS];                 // spatial hash index
__device__ int   d_cnt[BB * NPSP];               // per-batch global histogram
__device__ float d_Pall[NL * NPSP * HID];        // projected spatial patterns, all layers
__device__ float d_gw[BB];                       // gate weight w1 per batch

// ---------------- twiddles (float sinpi/cospi; args 2m/S exact in fp32) ----------------
__global__ void k_init_tw() {
    int i = blockIdx.x * 256 + threadIdx.x;        // i < NM*SH
    int k = i >> 13, s = i & (SH - 1);
    int m = (s * k) & (SS - 1);
    float x = (float)(2 * m) / (float)SS;
    d_twcT[i] = cospif(x);
    d_twsT[i] = sinpif(x);
}

// ---------------- all-layer spatial pattern projection + initial d_cnt zero ----------------
__global__ void k_prep_all(const float* __restrict__ sp_emb, const float* __restrict__ sp_W,
                           const float* __restrict__ sp_b) {
    int i = blockIdx.x * 256 + threadIdx.x;        // NL*NPSP*HID = 128000
    if (i < BB * NPSP) d_cnt[i] = 0;
    if (i >= NL * NPSP * HID) return;
    int l = i / (NPSP * HID);
    int r = i - l * (NPSP * HID);
    int p = r / HID, c = r % HID;
    const float* e = sp_emb + (l * NPSP + p) * ED;
    const float* W = sp_W + l * ED * HID;
    float acc = sp_b[l * HID + c];
#pragma unroll
    for (int j = 0; j < ED; j++) acc = fmaf(e[j], W[j * HID + c], acc);
    d_Pall[i] = acc;
}

// ---------------- layer-0: lift fused with paired forward DFT ----------------
// grid (NCH=32, B). Block: 256 pairs (s, s+8192) in 8 pieces of 32 pairs.
// h tile computed from x in smem (hp/hm); h never written to global.
// Thread: g = t&15 -> cols {g, 16+g}; c4 = t>>4 -> channels {4c4..+3}.
__global__ void __launch_bounds__(256) k_fwd1_lift(const float* __restrict__ x,
                                                   const float* __restrict__ liftW,
                                                   const float* __restrict__ liftb) {
    __shared__ float sh_hp[64][36];
    __shared__ float sh_hm[64][36];
    __shared__ float shT[2][32][36];
    __shared__ float shWs[4];                      // colsum(W0),(W1),(W2), colsum(b)
    int chunk = blockIdx.x, b = blockIdx.y, t = threadIdx.x;
    int g = t & 15, c4 = t >> 4;
    int ps0 = chunk * 256;

    if (t < 4) {
        float acc = 0.f;
        if (t < 3) { for (int c = 0; c < HID; c++) acc += __ldg(&liftW[t * HID + c]); }
        else       { for (int c = 0; c < HID; c++) acc += __ldg(&liftb[c]); }
        shWs[t] = acc;
    }

    float f[4][2];
#pragma unroll
    for (int ci = 0; ci < 4; ci++) { f[ci][0] = 0.f; f[ci][1] = 0.f; }

    const float* x0p = x + (b * CIN + 0) * SS;
    const float* x1p = x + (b * CIN + 1) * SS;
    const float* x2p = x + (b * CIN + 2) * SS;

    for (int piece = 0; piece < 8; piece++) {
        int pp0 = ps0 + piece * 32;
        int pb = piece & 1;
        {
            int col = t >> 3, j4 = (t & 7) * 4;
            float4 v;
            if (col < 16) v = *(const float4*)&d_twcT[col * SH + pp0 + j4];
            else          v = *(const float4*)&d_twsT[(col - 16) * SH + pp0 + j4];
            *(float4*)&shT[pb][col][j4] = v;
        }
        // lift on the fly -> hp/hm tiles
        for (int u = t; u < 512; u += 256) {
            int c = u >> 3, j4 = (u & 7) * 4;
            float w0 = __ldg(&liftW[c]);
            float w1 = __ldg(&liftW[HID + c]);
            float w2 = __ldg(&liftW[2 * HID + c]);
            float bc = __ldg(&liftb[c]);
            float4 a0 = *(const float4*)&x0p[pp0 + j4];
            float4 a1 = *(const float4*)&x1p[pp0 + j4];
            float4 a2 = *(const float4*)&x2p[pp0 + j4];
            float4 b0 = *(const float4*)&x0p[SH + pp0 + j4];
            float4 b1 = *(const float4*)&x1p[SH + pp0 + j4];
            float4 b2 = *(const float4*)&x2p[SH + pp0 + j4];
            float h1x = fmaf(a0.x, w0, fmaf(a1.x, w1, fmaf(a2.x, w2, bc)));
            float h1y = fmaf(a0.y, w0, fmaf(a1.y, w1, fmaf(a2.y, w2, bc)));
            float h1z = fmaf(a0.z, w0, fmaf(a1.z, w1, fmaf(a2.z, w2, bc)));
            float h1w = fmaf(a0.w, w0, fmaf(a1.w, w1, fmaf(a2.w, w2, bc)));
            float h2x = fmaf(b0.x, w0, fmaf(b1.x, w1, fmaf(b2.x, w2, bc)));
            float h2y = fmaf(b0.y, w0, fmaf(b1.y, w1, fmaf(b2.y, w2, bc)));
            float h2z = fmaf(b0.z, w0, fmaf(b1.z, w1, fmaf(b2.z, w2, bc)));
            float h2w = fmaf(b0.w, w0, fmaf(b1.w, w1, fmaf(b2.w, w2, bc)));
            *(float4*)&sh_hp[c][j4] = make_float4(h1x + h2x, h1y + h2y, h1z + h2z, h1w + h2w);
            *(float4*)&sh_hm[c][j4] = make_float4(h1x - h2x, h1y - h2y, h1z - h2z, h1w - h2w);
        }
        __syncthreads();

        // channel sums via exact linear functional (same value to fp rounding)
        if (t < 64) {
            int j = t & 31;
            int s = pp0 + j + ((t >> 5) ? SH : 0);
            float cs = fmaf(x0p[s], shWs[0], fmaf(x1p[s], shWs[1], fmaf(x2p[s], shWs[2], shWs[3])));
            d_sC[b * SS + s] = cs;
        }

        const float (*hb)[36] = (g & 1) ? (const float (*)[36])sh_hm : (const float (*)[36])sh_hp;
#pragma unroll
        for (int q = 0; q < 8; q++) {
            float4 t0 = *(const float4*)&shT[pb][g][q * 4];
            float4 t1 = *(const float4*)&shT[pb][g + 16][q * 4];
#pragma unroll
            for (int ci = 0; ci < 4; ci++) {
                float4 hv = *(const float4*)&hb[c4 * 4 + ci][q * 4];
                f[ci][0] = fmaf(hv.x, t0.x, fmaf(hv.y, t0.y, fmaf(hv.z, t0.z, fmaf(hv.w, t0.w, f[ci][0]))));
                f[ci][1] = fmaf(hv.x, t1.x, fmaf(hv.y, t1.y, fmaf(hv.z, t1.z, fmaf(hv.w, t1.w, f[ci][1]))));
            }
        }
        __syncthreads();                            // protects hp/hm overwrite next piece
    }
    float* p = &d_part[((size_t)(b * NCH + chunk) * HID + c4 * 4) * 32];
#pragma unroll
    for (int ci = 0; ci < 4; ci++) {
        p[ci * 32 + g]      = f[ci][0];
        p[ci * 32 + 16 + g] = f[ci][1];
    }
}

// ---------------- aux: spectrum reduce (chunk<8) + spatial hash + histogram ----------------
__global__ void __launch_bounds__(256) k_aux() {
    __shared__ int hist[NPSP];
    int b = blockIdx.y, chunk = blockIdx.x, t = threadIdx.x;
    for (int i = t; i < NPSP; i += 256) hist[i] = 0;

    if (chunk < 8) {                               // 8x16 blocks x 256 t = 32768 entries
        int u = chunk * 256 + t;
        const float* p = d_part + (size_t)b * NCH * 2048 + u;
        double acc = 0.0;
#pragma unroll 8
        for (int ch = 0; ch < NCH; ch++) acc += (double)p[(size_t)ch * 2048];
        d_Xf[b * 2048 + u] = (float)acc;
    }
    __syncthreads();

    int s = chunk * 256 + t;
    const float* sc = d_sC + b * SS;
    int a0 = max(s - 2, 0), a1 = max(s - 1, 0), a3 = min(s + 1, SS - 1);
    float w = ((sc[a0] + sc[a1]) + sc[s]) + sc[a3];
    int iv = (int)(w * 31.0f);
    int m = iv % NPSP; if (m < 0) m += NPSP;
    d_idx[b * SS + s] = m;
    atomicAdd(&hist[m], 1);
    __syncthreads();
    for (int i = t; i < NPSP; i += 256)
        if (hist[i]) atomicAdd(&d_cnt[b * NPSP + i], hist[i]);
}

// ---------------- per-batch: spectral mix + gate + combined spectrum ----------------
__global__ void __launch_bounds__(256) k_mix(
        const float* __restrict__ fr_emb, const float* __restrict__ fr_W,
        const float* __restrict__ fr_b,
        const float* __restrict__ mhf_Wr, const float* __restrict__ mhf_Wi,
        const float* __restrict__ gW1, const float* __restrict__ gb1,
        const float* __restrict__ gW2, const float* __restrict__ gb2,
        int layer) {
    __shared__ float shX[HID * 32];
    __shared__ float shMHre[HID * NM];
    __shared__ float shMHim[HID * NM];
    __shared__ float shFR[HID * NM];
    __shared__ double shmagp[4][16];
    __shared__ double shgp[4][64];
    __shared__ float shg[192];
    __shared__ float shhid[64];
    __shared__ float shw[3];
    __shared__ int   shmi[16];
    __shared__ int   sh_ifr;
    int b = blockIdx.x, t = threadIdx.x;

    for (int i = t; i < HID * 32; i += 256) shX[i] = d_Xf[b * HID * 32 + i];
    __syncthreads();

    // spectral magnitude hash: 4 fixed-order fp64 slices of 16 channels
    if (t < 64) {
        int k = t & 15, sl = t >> 4;
        double acc = 0.0;
        for (int c = sl * 16; c < sl * 16 + 16; c++) {
            double re = (double)shX[c * 32 + k];
            double im = (double)shX[c * 32 + 16 + k];
            acc += sqrt(re * re + im * im);
        }
        shmagp[sl][k] = acc;
    }
    // multi-head Fourier mix
    for (int u = t; u < 1024; u += 256) {            // u = h*256 + o*16 + k
        int h_ = u >> 8, o = (u >> 4) & 15, k = u & 15;
        float ar = 0.f, ai = 0.f;
        const float* Wr = mhf_Wr + (((layer * 4 + h_) * 16) * 16 + o) * 16 + k;
        const float* Wi = mhf_Wi + (((layer * 4 + h_) * 16) * 16 + o) * 16 + k;
#pragma unroll
        for (int i = 0; i < 16; i++) {
            int cin = h_ * 16 + i;
            float re = shX[cin * 32 + k];
            float im = -shX[cin * 32 + 16 + k];
            float wr = Wr[i * 256];
            float wi = Wi[i * 256];
            ar = fmaf(re, wr, ar); ar = fmaf(-im, wi, ar);
            ai = fmaf(re, wi, ai); ai = fmaf(im, wr, ai);
        }
        int cout = h_ * 16 + o;
        shMHre[cout * 16 + k] = ar;
        shMHim[cout * 16 + k] = ai;
    }
    __syncthreads();
    if (t < 16) {
        double acc = ((shmagp[0][t] + shmagp[1][t]) + shmagp[2][t]) + shmagp[3][t];
        float mag = (float)(acc / 64.0);
        shmi[t] = (int)(mag * 1000.0f);
    }
    __syncthreads();
    if (t == 0) {
        int ssum = 0;
        for (int k = 0; k < 16; k++) ssum += shmi[k];
        int m = ssum % NPFR; if (m < 0) m += NPFR;
        sh_ifr = m;
    }
    __syncthreads();
    // spectral engram projection
    {
        const float* e = fr_emb + (layer * NPFR + sh_ifr) * ED;
        for (int u = t; u < 1024; u += 256) {        // u = c*16+k
            const float* W = fr_W + layer * ED * 1024 + u;
            float acc = fr_b[layer * 1024 + u];
#pragma unroll
            for (int j = 0; j < ED; j++) acc = fmaf(e[j], W[j * 1024], acc);
            shFR[u] = acc;
        }
    }
    // gate spatial mean: 4 fixed-order fp64 slices of 125 patterns
    {
        int c = t & 63, sl = t >> 6;
        double acc = 0.0;
        const float* P = d_Pall + layer * NPSP * HID;
        const int* cnt = d_cnt + b * NPSP;
        for (int p = sl * 125; p < sl * 125 + 125; p++)
            acc += (double)cnt[p] * (double)P[p * HID + c];
        shgp[sl][c] = acc;
    }
    __syncthreads();
    // all d_cnt reads complete -> zero it for the next layer's hash
    for (int i = t; i < NPSP; i += 256) d_cnt[b * NPSP + i] = 0;
    if (t < 64) {
        double acc = ((shgp[0][t] + shgp[1][t]) + shgp[2][t]) + shgp[3][t];
        shg[t]       = (float)(acc / (double)SS);
        shg[64 + t]  = shMHre[t * 16 + 0] / (float)SS;
        shg[128 + t] = shFR[t * 16 + 0] / (float)SS;
    }
    __syncthreads();
    if (t < 64) {
        float acc = gb1[layer * 64 + t];
        const float* W1 = gW1 + layer * 192 * 64;
        for (int j = 0; j < 192; j++) acc = fmaf(shg[j], W1[j * 64 + t], acc);
        shhid[t] = fmaxf(acc, 0.f);
    }
    __syncthreads();
    if (t == 0) {
        float lg[3];
        const float* W2 = gW2 + layer * 64 * 3;
        for (int o = 0; o < 3; o++) {
            float acc = gb2[layer * 3 + o];
            for (int j = 0; j < 64; j++) acc = fmaf(shhid[j], W2[j * 3 + o], acc);
            lg[o] = acc;
        }
        float mx = fmaxf(lg[0], fmaxf(lg[1], lg[2]));
        float e0 = expf(lg[0] - mx), e1 = expf(lg[1] - mx), e2 = expf(lg[2] - mx);
        float inv = 1.f / (e0 + e1 + e2);
        shw[0] = e0 * inv; shw[1] = e1 * inv; shw[2] = e2 * inv;
        d_gw[b] = shw[0];
    }
    __syncthreads();
    // combined, irfft-prescaled spectrum
    float w2 = shw[1], w3 = shw[2];
    for (int u = t; u < 1024; u += 256) {            // u = c*16+k
        int k = u & 15;
        int c = u >> 4;
        float sc = ((k == 0) ? 1.f : 2.f) / (float)SS;
        d_Cf[(b * HID + c) * 32 + k]      = (w2 * shMHre[u] + w3 * shFR[u]) * sc;
        d_Cf[(b * HID + c) * 32 + 16 + k] = (w2 * shMHim[u]) * sc;
    }
}

// ---------------- fused transition (paired): comb(layer) -> gelu -> fwd partials ----------------
// comb: E = sum_{K even} A[K][c]T[K][s], O = sum_{K odd}; h(s)=E+O, h(s+SH)=E-O. gelu both.
// Then hp=g1+g2, hm=g1-g2 -> fwd cols even/odd consume hp/hm. h never hits global.
// shT double-buffered: 2 syncs/piece (sync1 of piece p+1 orders fwd-GEMM(p) before epilogue(p+1)).
__global__ void __launch_bounds__(256) k_fused(int layer) {
    __shared__ float shA[32][68];                  // [K][channel]
    __shared__ float shT[2][32][36];               // [K][pair s_local], double-buffered
    __shared__ float sh_hp[64][36];
    __shared__ float sh_hm[64][36];
    __shared__ float shCS[16][68];                 // per-c4 channel sums, 64 sample cols
    int b = blockIdx.y, chunk = blockIdx.x, t = threadIdx.x;
    int g = t & 15, c4 = t >> 4;
    int ps0 = chunk * 256;

    for (int u = t; u < 2048; u += 256) {
        int K = u >> 6, c = u & 63;
        float v = (K < 16) ? d_Cf[b * 2048 + c * 32 + K]
                           : -d_Cf[b * 2048 + c * 32 + 16 + (K - 16)];
        shA[K][c] = v;
    }
    float w1 = d_gw[b];

    float f[4][2];
#pragma unroll
    for (int ci = 0; ci < 4; ci++) { f[ci][0] = 0.f; f[ci][1] = 0.f; }

    for (int piece = 0; piece < 8; piece++) {
        int pp0 = ps0 + piece * 32;
        int pb = piece & 1;
        {
            int col = t >> 3, j4 = (t & 7) * 4;
            float4 v;
            if (col < 16) v = *(const float4*)&d_twcT[col * SH + pp0 + j4];
            else          v = *(const float4*)&d_twsT[(col - 16) * SH + pp0 + j4];
            *(float4*)&shT[pb][col][j4] = v;
        }
        __syncthreads();                           // shT ready; fwd-GEMM of prev piece done

        // ---- comb GEMM: even/odd-K accumulation, 4ch x 2 pairs ----
        float aE[4][2], aO[4][2];
#pragma unroll
        for (int ci = 0; ci < 4; ci++) { aE[ci][0] = aE[ci][1] = 0.f; aO[ci][0] = aO[ci][1] = 0.f; }
#pragma unroll
        for (int K = 0; K < 32; K += 2) {
            {
                float4 a  = *(const float4*)&shA[K][c4 * 4];
                float2 tv = *(const float2*)&shT[pb][K][g * 2];
                aE[0][0] = fmaf(a.x, tv.x, aE[0][0]); aE[0][1] = fmaf(a.x, tv.y, aE[0][1]);
                aE[1][0] = fmaf(a.y, tv.x, aE[1][0]); aE[1][1] = fmaf(a.y, tv.y, aE[1][1]);
                aE[2][0] = fmaf(a.z, tv.x, aE[2][0]); aE[2][1] = fmaf(a.z, tv.y, aE[2][1]);
                aE[3][0] = fmaf(a.w, tv.x, aE[3][0]); aE[3][1] = fmaf(a.w, tv.y, aE[3][1]);
            }
            {
                float4 a  = *(const float4*)&shA[K + 1][c4 * 4];
                float2 tv = *(const float2*)&shT[pb][K + 1][g * 2];
                aO[0][0] = fmaf(a.x, tv.x, aO[0][0]); aO[0][1] = fmaf(a.x, tv.y, aO[0][1]);
                aO[1][0] = fmaf(a.y, tv.x, aO[1][0]); aO[1][1] = fmaf(a.y, tv.y, aO[1][1]);
                aO[2][0] = fmaf(a.z, tv.x, aO[2][0]); aO[2][1] = fmaf(a.z, tv.y, aO[2][1]);
                aO[3][0] = fmaf(a.w, tv.x, aO[3][0]); aO[3][1] = fmaf(a.w, tv.y, aO[3][1]);
            }
        }

        // ---- epilogue: engram + exact gelu for both halves; stash hp/hm ----
        int2 i1 = *(const int2*)&d_idx[b * SS + pp0 + g * 2];
        int2 i2 = *(const int2*)&d_idx[b * SS + SH + pp0 + g * 2];
        int idx1[2] = {i1.x, i1.y};
        int idx2[2] = {i2.x, i2.y};
#pragma unroll
        for (int pr = 0; pr < 2; pr++) {
            float4 P1 = *(const float4*)&d_Pall[(layer * NPSP + idx1[pr]) * HID + c4 * 4];
            float4 P2 = *(const float4*)&d_Pall[(layer * NPSP + idx2[pr]) * HID + c4 * 4];
            float pv1[4] = {P1.x, P1.y, P1.z, P1.w};
            float pv2[4] = {P2.x, P2.y, P2.z, P2.w};
            float cs1 = 0.f, cs2 = 0.f;
#pragma unroll
            for (int ci = 0; ci < 4; ci++) {
                float h1 = aE[ci][pr] + aO[ci][pr];
                float h2 = aE[ci][pr] - aO[ci][pr];
                float v1 = fmaf(w1, pv1[ci], h1);
                float v2 = fmaf(w1, pv2[ci], h2);
                float g1 = 0.5f * v1 * (1.f + erff(v1 * 0.70710678118654752f));
                float g2 = 0.5f * v2 * (1.f + erff(v2 * 0.70710678118654752f));
                sh_hp[c4 * 4 + ci][g * 2 + pr] = g1 + g2;
                sh_hm[c4 * 4 + ci][g * 2 + pr] = g1 - g2;
                cs1 += g1; cs2 += g2;
            }
            shCS[c4][g * 2 + pr]      = cs1;
            shCS[c4][32 + g * 2 + pr] = cs2;
        }
        __syncthreads();

        if (t < 64) {
            float ss = 0.f;
#pragma unroll
            for (int q = 0; q < 16; q++) ss += shCS[q][t];   // fixed order
            if (t < 32) d_sC[b * SS + pp0 + t] = ss;
            else        d_sC[b * SS + SH + pp0 + t - 32] = ss;
        }

        // ---- fwd GEMM on fresh tile: cols {g, 16+g}, parity selects hp/hm ----
        const float (*hb)[36] = (g & 1) ? (const float (*)[36])sh_hm : (const float (*)[36])sh_hp;
#pragma unroll
        for (int q = 0; q < 8; q++) {
            float4 t0 = *(const float4*)&shT[pb][g][q * 4];
            float4 t1 = *(const float4*)&shT[pb][g + 16][q * 4];
#pragma unroll
            for (int ci = 0; ci < 4; ci++) {
                float4 hv = *(const float4*)&hb[c4 * 4 + ci][q * 4];
                f[ci][0] = fmaf(hv.x, t0.x, fmaf(hv.y, t0.y, fmaf(hv.z, t0.z, fmaf(hv.w, t0.w, f[ci][0]))));
                f[ci][1] = fmaf(hv.x, t1.x, fmaf(hv.y, t1.y, fmaf(hv.z, t1.z, fmaf(hv.w, t1.w, f[ci][1]))));
            }
        }
        // no end-of-piece sync: next piece's first sync orders fwd reads vs epilogue writes
    }
    float* p = &d_part[((size_t)(b * NCH + chunk) * HID + c4 * 4) * 32];
#pragma unroll
    for (int ci = 0; ci < 4; ci++) {
        p[ci * 32 + g]      = f[ci][0];
        p[ci * 32 + 16 + g] = f[ci][1];
    }
}

// ---------------- final combine (paired) + output projection ----------------
__global__ void __launch_bounds__(256) k_comb_last(const float* __restrict__ projW,
                                                   const float* __restrict__ projb,
                                                   float* __restrict__ out) {
    const int layer = NL - 1;
    __shared__ float shA[32][68];
    __shared__ float shT[2][32][36];
    __shared__ float shCS[16][68];
    int b = blockIdx.y, chunk = blockIdx.x, t = threadIdx.x;
    int g = t & 15, c4 = t >> 4;
    int ps0 = chunk * 256;

    for (int u = t; u < 2048; u += 256) {
        int K = u >> 6, c = u & 63;
        float v = (K < 16) ? d_Cf[b * 2048 + c * 32 + K]
                           : -d_Cf[b * 2048 + c * 32 + 16 + (K - 16)];
        shA[K][c] = v;
    }
    float w1 = d_gw[b];
    float4 PW = *(const float4*)&projW[c4 * 4];
    float pw[4] = {PW.x, PW.y, PW.z, PW.w};

    for (int piece = 0; piece < 8; piece++) {
        int pp0 = ps0 + piece * 32;
        int pb = piece & 1;
        {
            int col = t >> 3, j4 = (t & 7) * 4;
            float4 v;
            if (col < 16) v = *(const float4*)&d_twcT[col * SH + pp0 + j4];
            else          v = *(const float4*)&d_twsT[(col - 16) * SH + pp0 + j4];
            *(float4*)&shT[pb][col][j4] = v;
        }
        __syncthreads();

        float aE[4][2], aO[4][2];
#pragma unroll
        for (int ci = 0; ci < 4; ci++) { aE[ci][0] = aE[ci][1] = 0.f; aO[ci][0] = aO[ci][1] = 0.f; }
#pragma unroll
        for (int K = 0; K < 32; K += 2) {
            {
                float4 a  = *(const float4*)&shA[K][c4 * 4];
                float2 tv = *(const float2*)&shT[pb][K][g * 2];
                aE[0][0] = fmaf(a.x, tv.x, aE[0][0]); aE[0][1] = fmaf(a.x, tv.y, aE[0][1]);
                aE[1][0] = fmaf(a.y, tv.x, aE[1][0]); aE[1][1] = fmaf(a.y, tv.y, aE[1][1]);
                aE[2][0] = fmaf(a.z, tv.x, aE[2][0]); aE[2][1] = fmaf(a.z, tv.y, aE[2][1]);
                aE[3][0] = fmaf(a.w, tv.x, aE[3][0]); aE[3][1] = fmaf(a.w, tv.y, aE[3][1]);
            }
            {
                float4 a  = *(const float4*)&shA[K + 1][c4 * 4];
                float2 tv = *(const float2*)&shT[pb][K + 1][g * 2];
                aO[0][0] = fmaf(a.x, tv.x, aO[0][0]); aO[0][1] = fmaf(a.x, tv.y, aO[0][1]);
                aO[1][0] = fmaf(a.y, tv.x, aO[1][0]); aO[1][1] = fmaf(a.y, tv.y, aO[1][1]);
                aO[2][0] = fmaf(a.z, tv.x, aO[2][0]); aO[2][1] = fmaf(a.z, tv.y, aO[2][1]);
                aO[3][0] = fmaf(a.w, tv.x, aO[3][0]); aO[3][1] = fmaf(a.w, tv.y, aO[3][1]);
            }
        }

        int2 i1 = *(const int2*)&d_idx[b * SS + pp0 + g * 2];
        int2 i2 = *(const int2*)&d_idx[b * SS + SH + pp0 + g * 2];
        int idx1[2] = {i1.x, i1.y};
        int idx2[2] = {i2.x, i2.y};
#pragma unroll
        for (int pr = 0; pr < 2; pr++) {
            float4 P1 = *(const float4*)&d_Pall[(layer * NPSP + idx1[pr]) * HID + c4 * 4];
            float4 P2 = *(const float4*)&d_Pall[(layer * NPSP + idx2[pr]) * HID + c4 * 4];
            float pv1[4] = {P1.x, P1.y, P1.z, P1.w};
            float pv2[4] = {P2.x, P2.y, P2.z, P2.w};
            float ps1 = 0.f, ps2 = 0.f;
#pragma unroll
            for (int ci = 0; ci < 4; ci++) {
                float h1 = aE[ci][pr] + aO[ci][pr];
                float h2 = aE[ci][pr] - aO[ci][pr];
                float v1 = fmaf(w1, pv1[ci], h1);
                float v2 = fmaf(w1, pv2[ci], h2);
                float g1 = 0.5f * v1 * (1.f + erff(v1 * 0.70710678118654752f));
                float g2 = 0.5f * v2 * (1.f + erff(v2 * 0.70710678118654752f));
                ps1 = fmaf(g1, pw[ci], ps1);
                ps2 = fmaf(g2, pw[ci], ps2);
            }
            shCS[c4][g * 2 + pr]      = ps1;
            shCS[c4][32 + g * 2 + pr] = ps2;
        }
        __syncthreads();
        if (t < 64) {
            float ss = 0.f;
#pragma unroll
            for (int q = 0; q < 16; q++) ss += shCS[q][t];
            if (t < 32) out[b * SS + pp0 + t] = ss + projb[0];
            else        out[b * SS + SH + pp0 + t - 32] = ss + projb[0];
        }
        // no end-of-piece sync: next piece's first sync orders shCS reads vs next writes
    }
}

// ---------------- host ----------------
extern "C" void kernel_launch(void* const* d_in, const int* in_sizes, int n_in,
                              void* d_out, int out_size) {
    const float* x      = (const float*)d_in[0];
    const float* lift_W = (const float*)d_in[1];
    const float* lift_b = (const float*)d_in[2];
    const float* proj_W = (const float*)d_in[3];
    const float* proj_b = (const float*)d_in[4];
    const float* sp_emb = (const float*)d_in[5];
    const float* sp_W   = (const float*)d_in[6];
    const float* sp_b   = (const float*)d_in[7];
    const float* fr_emb = (const float*)d_in[8];
    const float* fr_W   = (const float*)d_in[9];
    const float* fr_b   = (const float*)d_in[10];
    const float* gW1    = (const float*)d_in[11];
    const float* gb1    = (const float*)d_in[12];
    const float* gW2    = (const float*)d_in[13];
    const float* gb2    = (const float*)d_in[14];
    const float* mhf_Wr = (const float*)d_in[15];
    const float* mhf_Wi = (const float*)d_in[16];
    float* out = (float*)d_out;

    k_init_tw<<<(NM * SH) / 256, 256>>>();
    k_prep_all<<<(NL * NPSP * HID + 255) / 256, 256>>>(sp_emb, sp_W, sp_b);

    for (int l = 0; l < NL; l++) {
        if (l == 0) k_fwd1_lift<<<dim3(NCH, BB), 256>>>(x, lift_W, lift_b);
        else        k_fused<<<dim3(NCH, BB), 256>>>(l - 1);
        k_aux<<<dim3(64, BB), 256>>>();
        k_mix<<<BB, 256>>>(fr_emb, fr_W, fr_b, mhf_Wr, mhf_Wi, gW1, gb1, gW2, gb2, l);
    }
    k_comb_last<<<dim3(NCH, BB), 256>>>(proj_W, proj_b, out);
}